// round 2
// baseline (speedup 1.0000x reference)
#include <cuda_runtime.h>
#include <cuda_bf16.h>
#include <math.h>

// Problem constants
#define B_   8
#define T_   512
#define D_   512
#define NH_  8
#define DH_  64

#define TQ 8     // query rows per attention block
#define TS 16    // s-tile

// Scratch (static device arrays; no allocations allowed)
__device__ float g_Q[B_ * NH_ * T_ * DH_];   // [b][h][t][d]
__device__ float g_K[B_ * NH_ * T_ * DH_];
__device__ float g_V[B_ * NH_ * T_ * DH_];
__device__ float g_ctx[B_ * T_ * D_];        // [b][t][h*64+d]

// ---------------------------------------------------------------------------
// GEMM: C[i,j] = sum_k A[i,k] * W[j,k] + bias[j]
// A: [4096, 512] row-major, W: [512, 512] row-major (as [j][k])
// DST 0/1/2 -> write g_Q/g_K/g_V in [b,h,t,d] layout;  DST 3 -> write Cout [i*512+j]
// 64x64 tile, 256 threads, 4x4 micro-tile, k-chunk 16.
// ---------------------------------------------------------------------------
template <int DST>
__global__ __launch_bounds__(256) void gemm_k(const float* __restrict__ A,
                                              const float* __restrict__ W,
                                              const float* __restrict__ bias,
                                              float* __restrict__ Cout) {
    __shared__ float Xs[16][68];
    __shared__ float Ws[16][68];

    const float* Ap = (DST == 3) ? (const float*)g_ctx : A;

    const int i0 = blockIdx.x * 64;
    const int j0 = blockIdx.y * 64;
    const int tid = threadIdx.x;
    const int tx = tid & 15;   // i direction (4 rows)
    const int ty = tid >> 4;   // j direction (4 cols)

    const int li = tid >> 2;   // load row 0..63
    const int lq = tid & 3;    // load k4-group 0..3

    float acc[4][4];
#pragma unroll
    for (int a = 0; a < 4; a++)
#pragma unroll
        for (int b = 0; b < 4; b++) acc[a][b] = 0.f;

    for (int kk = 0; kk < 512; kk += 16) {
        __syncthreads();
        float4 xa = *(const float4*)&Ap[(size_t)(i0 + li) * 512 + kk + lq * 4];
        float4 wa = *(const float4*)&W[(size_t)(j0 + li) * 512 + kk + lq * 4];
        Xs[lq * 4 + 0][li] = xa.x; Xs[lq * 4 + 1][li] = xa.y;
        Xs[lq * 4 + 2][li] = xa.z; Xs[lq * 4 + 3][li] = xa.w;
        Ws[lq * 4 + 0][li] = wa.x; Ws[lq * 4 + 1][li] = wa.y;
        Ws[lq * 4 + 2][li] = wa.z; Ws[lq * 4 + 3][li] = wa.w;
        __syncthreads();

#pragma unroll
        for (int k = 0; k < 16; k++) {
            float4 a = *(const float4*)&Xs[k][tx * 4];
            float4 b = *(const float4*)&Ws[k][ty * 4];
            acc[0][0] += a.x * b.x; acc[0][1] += a.x * b.y; acc[0][2] += a.x * b.z; acc[0][3] += a.x * b.w;
            acc[1][0] += a.y * b.x; acc[1][1] += a.y * b.y; acc[1][2] += a.y * b.z; acc[1][3] += a.y * b.w;
            acc[2][0] += a.z * b.x; acc[2][1] += a.z * b.y; acc[2][2] += a.z * b.z; acc[2][3] += a.z * b.w;
            acc[3][0] += a.w * b.x; acc[3][1] += a.w * b.y; acc[3][2] += a.w * b.z; acc[3][3] += a.w * b.w;
        }
    }

#pragma unroll
    for (int ii = 0; ii < 4; ii++) {
        const int i = i0 + tx * 4 + ii;
#pragma unroll
        for (int jj = 0; jj < 4; jj++) {
            const int j = j0 + ty * 4 + jj;
            float v = acc[ii][jj] + bias[j];
            if (DST == 3) {
                Cout[(size_t)i * 512 + j] = v;
            } else {
                const int b = i >> 9, t = i & 511;
                const int h = j >> 6, dh = j & 63;
                float* dst = (DST == 0) ? g_Q : (DST == 1) ? g_K : g_V;
                dst[(((b * NH_ + h) * T_) + t) * DH_ + dh] = v;
            }
        }
    }
}

// ---------------------------------------------------------------------------
// Attention: one block per (head, 8-query tile), covering all 8 batches.
// score[b,t,s] = (Q[b,h,t,:].K[b,h,s,:] + Q[b,h,t,:].rel[t,s,h*64:]) / 8
// Flash-style online softmax over s in tiles of 16; ctx accumulated in regs.
// ---------------------------------------------------------------------------
#define QS_OFF  0
#define KS_OFF  (QS_OFF + 64 * 64)            // 4096
#define VS_OFF  (KS_OFF + TS * B_ * DH_)      // +8192
#define RS_OFF  (VS_OFF + TS * B_ * DH_)      // +8192
#define SS_OFF  (RS_OFF + TQ * TS * DH_)      // +8192
#define RM_OFF  (SS_OFF + 64 * 17)            // +1088
#define RL_OFF  (RM_OFF + 64)
#define RC_OFF  (RL_OFF + 64)
#define SMEM_FLOATS (RC_OFF + 64)
#define SMEM_BYTES  (SMEM_FLOATS * 4)

__global__ __launch_bounds__(512, 1) void attn_kernel(const float* __restrict__ rel) {
    const int h = blockIdx.y;
    const int t0 = blockIdx.x * TQ;

    extern __shared__ float sm[];
    float* Qs   = sm + QS_OFF;   // [row=b*8+tq][d]
    float* Ks   = sm + KS_OFF;   // [sl][b][d]
    float* Vs   = sm + VS_OFF;   // [sl][b][d]
    float* Rs   = sm + RS_OFF;   // [tq][sl][d]
    float* Ss   = sm + SS_OFF;   // [row][sl] pad 17
    float* rowm = sm + RM_OFF;
    float* rowl = sm + RL_OFF;
    float* rowsc = sm + RC_OFF;

    const int tid = threadIdx.x;

    // Load Q tile: 64 rows x 64 d = 1024 float4
#pragma unroll
    for (int p = 0; p < 2; p++) {
        int f = tid + p * 512;
        int row = f >> 4, dq = f & 15;
        int b = row >> 3, tq = row & 7;
        const float4* src = (const float4*)&g_Q[(((b * NH_ + h) * T_) + t0 + tq) * DH_];
        ((float4*)&Qs[row * 64])[dq] = src[dq];
    }
    if (tid < 64) { rowm[tid] = -1e30f; rowl[tid] = 0.f; }

    float ctx[8];
#pragma unroll
    for (int i = 0; i < 8; i++) ctx[i] = 0.f;

    const int row  = tid >> 3;     // 0..63 (= b*8 + tq)
    const int lane8 = tid & 7;     // score phase: slg ; AV phase: dseg
    const int b_r  = row >> 3;
    const int tq_r = row & 7;

    for (int s0 = 0; s0 < T_; s0 += TS) {
        __syncthreads();   // smem tiles free to overwrite

        // Load K, V (8192 fl each) and rel (8192 fl): 2048 float4 each, 4/thread
#pragma unroll
        for (int p = 0; p < 4; p++) {
            int f  = tid + p * 512;
            int dq = f & 15;
            int sb = f >> 4;             // 0..127
            int bb = sb & 7, sl = sb >> 3;
            const float4* srcK = (const float4*)&g_K[(((bb * NH_ + h) * T_) + s0 + sl) * DH_];
            ((float4*)&Ks[(sl * 8 + bb) * 64])[dq] = srcK[dq];
            const float4* srcV = (const float4*)&g_V[(((bb * NH_ + h) * T_) + s0 + sl) * DH_];
            ((float4*)&Vs[(sl * 8 + bb) * 64])[dq] = srcV[dq];
            int sl2 = sb & 15, tq2 = sb >> 4;
            const float4* srcR =
                (const float4*)&rel[((size_t)(t0 + tq2) * T_ + (s0 + sl2)) * D_ + h * DH_];
            ((float4*)&Rs[(tq2 * 16 + sl2) * 64])[dq] = srcR[dq];
        }
        __syncthreads();

        // Scores: 2 per thread (sl = lane8, lane8+8)
        {
            float a0 = 0.f, a1 = 0.f;
            const float* qp = &Qs[row * 64];
            const float* k0 = &Ks[(lane8 * 8 + b_r) * 64];
            const float* k1 = &Ks[((lane8 + 8) * 8 + b_r) * 64];
            const float* r0 = &Rs[(tq_r * 16 + lane8) * 64];
            const float* r1 = &Rs[(tq_r * 16 + lane8 + 8) * 64];
#pragma unroll
            for (int k = 0; k < 64; k += 4) {
                float4 q  = *(const float4*)(qp + k);
                float4 ka = *(const float4*)(k0 + k);
                float4 kb = *(const float4*)(k1 + k);
                float4 ra = *(const float4*)(r0 + k);
                float4 rb = *(const float4*)(r1 + k);
                a0 += q.x * ka.x; a0 += q.x * ra.x;
                a0 += q.y * ka.y; a0 += q.y * ra.y;
                a0 += q.z * ka.z; a0 += q.z * ra.z;
                a0 += q.w * ka.w; a0 += q.w * ra.w;
                a1 += q.x * kb.x; a1 += q.x * rb.x;
                a1 += q.y * kb.y; a1 += q.y * rb.y;
                a1 += q.z * kb.z; a1 += q.z * rb.z;
                a1 += q.w * kb.w; a1 += q.w * rb.w;
            }
            Ss[row * 17 + lane8]     = a0 * 0.125f;
            Ss[row * 17 + lane8 + 8] = a1 * 0.125f;
        }
        __syncthreads();

        // Online softmax stats (one thread per row)
        if (tid < 64) {
            float m_old = rowm[tid];
            float mt = m_old;
            float* srow = &Ss[tid * 17];
#pragma unroll
            for (int j = 0; j < 16; j++) mt = fmaxf(mt, srow[j]);
            float scale = __expf(m_old - mt);
            float l = rowl[tid] * scale;
#pragma unroll
            for (int j = 0; j < 16; j++) {
                float p = __expf(srow[j] - mt);
                srow[j] = p;
                l += p;
            }
            rowm[tid] = mt; rowl[tid] = l; rowsc[tid] = scale;
        }
        __syncthreads();

        // AV: thread owns ctx[row][dseg*8 .. +7]
        {
            const int dseg = lane8;
            float sc = rowsc[row];
#pragma unroll
            for (int i = 0; i < 8; i++) ctx[i] *= sc;
            const float* ps = &Ss[row * 17];
#pragma unroll
            for (int sl = 0; sl < TS; sl++) {
                float p = ps[sl];
                const float4* vp = (const float4*)&Vs[(sl * 8 + b_r) * 64 + dseg * 8];
                float4 v0 = vp[0], v1 = vp[1];
                ctx[0] += p * v0.x; ctx[1] += p * v0.y;
                ctx[2] += p * v0.z; ctx[3] += p * v0.w;
                ctx[4] += p * v1.x; ctx[5] += p * v1.y;
                ctx[6] += p * v1.z; ctx[7] += p * v1.w;
            }
        }
    }

    // Finalize: divide by l, write to g_ctx[b][t][h*64 + d]
    const float inv = 1.0f / rowl[row];
    float* dst = &g_ctx[((size_t)(b_r * T_ + t0 + tq_r)) * D_ + h * DH_ + lane8 * 8];
#pragma unroll
    for (int i = 0; i < 8; i++) dst[i] = ctx[i] * inv;
}

// ---------------------------------------------------------------------------
extern "C" void kernel_launch(void* const* d_in, const int* in_sizes, int n_in,
                              void* d_out, int out_size) {
    const float* x   = (const float*)d_in[0];
    const float* rel = (const float*)d_in[1];
    const float* Wq  = (const float*)d_in[2];
    const float* bq  = (const float*)d_in[3];
    const float* Wk  = (const float*)d_in[4];
    const float* bk  = (const float*)d_in[5];
    const float* Wv  = (const float*)d_in[6];
    const float* bv  = (const float*)d_in[7];
    const float* Wo  = (const float*)d_in[8];
    const float* bo  = (const float*)d_in[9];
    float* out = (float*)d_out;

    cudaFuncSetAttribute(attn_kernel, cudaFuncAttributeMaxDynamicSharedMemorySize, SMEM_BYTES);

    dim3 gg(64, 8);   // 4096/64 row tiles, 512/64 col tiles
    gemm_k<0><<<gg, 256>>>(x, Wq, bq, nullptr);
    gemm_k<1><<<gg, 256>>>(x, Wk, bk, nullptr);
    gemm_k<2><<<gg, 256>>>(x, Wv, bv, nullptr);

    attn_kernel<<<dim3(T_ / TQ, NH_), 512, SMEM_BYTES>>>(rel);

    gemm_k<3><<<gg, 256>>>(nullptr, Wo, bo, out);
}

// round 4
// speedup vs baseline: 2.9630x; 2.9630x over previous
#include <cuda_runtime.h>
#include <cuda_bf16.h>
#include <cstdint>
#include <math.h>

#define B_   8
#define T_   512
#define D_   512
#define NH_  8
#define DH_  64

#define TQ 8     // query rows per attention block
#define TS 16    // s-tile

// Scratch (static device arrays; no allocations allowed)
__device__ float g_Q[B_ * NH_ * T_ * DH_];   // [b][h][t][d]
__device__ float g_K[B_ * NH_ * T_ * DH_];
__device__ float g_V[B_ * NH_ * T_ * DH_];
__device__ float g_ctx[B_ * T_ * D_];        // [b][t][h*64+d]

// ---------------------------------------------------------------------------
// cp.async helpers
// ---------------------------------------------------------------------------
__device__ __forceinline__ void cp16(unsigned int smem_addr, const void* gptr) {
    asm volatile("cp.async.cg.shared.global [%0], [%1], 16;\n"
                 :: "r"(smem_addr), "l"(gptr));
}
__device__ __forceinline__ void cp_commit() {
    asm volatile("cp.async.commit_group;\n");
}
template <int N>
__device__ __forceinline__ void cp_wait() {
    asm volatile("cp.async.wait_group %0;\n" :: "n"(N));
}

// ---------------------------------------------------------------------------
// GEMM: C[i,j] = sum_k A[i,k] * W[j,k] + bias[j]
// ---------------------------------------------------------------------------
template <int DST>
__global__ __launch_bounds__(256) void gemm_k(const float* __restrict__ A,
                                              const float* __restrict__ W,
                                              const float* __restrict__ bias,
                                              float* __restrict__ Cout) {
    __shared__ float Xs[16][68];
    __shared__ float Ws[16][68];

    const float* Ap = (DST == 3) ? (const float*)g_ctx : A;

    const int i0 = blockIdx.x * 64;
    const int j0 = blockIdx.y * 64;
    const int tid = threadIdx.x;
    const int tx = tid & 15;
    const int ty = tid >> 4;
    const int li = tid >> 2;
    const int lq = tid & 3;

    float acc[4][4];
#pragma unroll
    for (int a = 0; a < 4; a++)
#pragma unroll
        for (int b = 0; b < 4; b++) acc[a][b] = 0.f;

    for (int kk = 0; kk < 512; kk += 16) {
        __syncthreads();
        float4 xa = *(const float4*)&Ap[(size_t)(i0 + li) * 512 + kk + lq * 4];
        float4 wa = *(const float4*)&W[(size_t)(j0 + li) * 512 + kk + lq * 4];
        Xs[lq * 4 + 0][li] = xa.x; Xs[lq * 4 + 1][li] = xa.y;
        Xs[lq * 4 + 2][li] = xa.z; Xs[lq * 4 + 3][li] = xa.w;
        Ws[lq * 4 + 0][li] = wa.x; Ws[lq * 4 + 1][li] = wa.y;
        Ws[lq * 4 + 2][li] = wa.z; Ws[lq * 4 + 3][li] = wa.w;
        __syncthreads();

#pragma unroll
        for (int k = 0; k < 16; k++) {
            float4 a = *(const float4*)&Xs[k][tx * 4];
            float4 b = *(const float4*)&Ws[k][ty * 4];
            acc[0][0] += a.x * b.x; acc[0][1] += a.x * b.y; acc[0][2] += a.x * b.z; acc[0][3] += a.x * b.w;
            acc[1][0] += a.y * b.x; acc[1][1] += a.y * b.y; acc[1][2] += a.y * b.z; acc[1][3] += a.y * b.w;
            acc[2][0] += a.z * b.x; acc[2][1] += a.z * b.y; acc[2][2] += a.z * b.z; acc[2][3] += a.z * b.w;
            acc[3][0] += a.w * b.x; acc[3][1] += a.w * b.y; acc[3][2] += a.w * b.z; acc[3][3] += a.w * b.w;
        }
    }

#pragma unroll
    for (int ii = 0; ii < 4; ii++) {
        const int i = i0 + tx * 4 + ii;
#pragma unroll
        for (int jj = 0; jj < 4; jj++) {
            const int j = j0 + ty * 4 + jj;
            float v = acc[ii][jj] + bias[j];
            if (DST == 3) {
                Cout[(size_t)i * 512 + j] = v;
            } else {
                const int b = i >> 9, t = i & 511;
                const int h = j >> 6, dh = j & 63;
                float* dst = (DST == 0) ? g_Q : (DST == 1) ? g_K : g_V;
                dst[(((b * NH_ + h) * T_) + t) * DH_ + dh] = v;
            }
        }
    }
}

// ---------------------------------------------------------------------------
// Attention v2: conflict-free smem + cp.async double buffering + shfl softmax
// Block: (head h, 8-query tile t0), covers all 8 batches. 512 threads.
// thread: row = tid>>3 (b*8+tq), lane8 = tid&7 (score: sl group / AV: d seg)
// ---------------------------------------------------------------------------
#define KSTR 68                         // K/R row stride (floats), bank-spread
#define VSTR 64
#define QS_OFF  0
#define KS_OFF  (QS_OFF + 64 * 64)                  // 4096
#define KBUF    (B_ * TS * KSTR)                    // 8704
#define VS_OFF  (KS_OFF + 2 * KBUF)                 // 21504
#define VBUF    (B_ * TS * VSTR)                    // 8192
#define RS_OFF  (VS_OFF + 2 * VBUF)                 // 37888
#define RBUF    (TQ * TS * KSTR)                    // 8704
#define SMEM_FLOATS (RS_OFF + 2 * RBUF)             // 55296
#define SMEM_BYTES  (SMEM_FLOATS * 4)               // 221184

__global__ __launch_bounds__(512, 1) void attn_kernel(const float* __restrict__ rel) {
    const int h = blockIdx.y;
    const int t0 = blockIdx.x * TQ;

    extern __shared__ float sm[];
    float* Qs = sm + QS_OFF;
    float* Ks = sm + KS_OFF;
    float* Vs = sm + VS_OFF;
    float* Rs = sm + RS_OFF;

    const int tid = threadIdx.x;
    const int row   = tid >> 3;     // 0..63 (= b*8 + tq)
    const int lane8 = tid & 7;
    const int b_r   = row >> 3;
    const int tq_r  = row & 7;

    const unsigned int smem_u32 = (unsigned int)__cvta_generic_to_shared(sm);

    // Issue loads for tile starting at s0 into buffer bi (12 x 16B per thread)
    auto issue_tile = [&](int s0, int bi) {
#pragma unroll
        for (int p = 0; p < 4; p++) {
            int f  = tid + p * 512;
            int dq4 = f & 15;
            int sbb = f >> 4;                  // 0..127
            int bb = sbb & 7, sl = sbb >> 3;
            const float* srcK = &g_K[(size_t)(((bb * NH_ + h) * T_) + s0 + sl) * DH_ + dq4 * 4];
            cp16(smem_u32 + (unsigned int)(KS_OFF + bi * KBUF + (bb * TS + sl) * KSTR + dq4 * 4) * 4, srcK);
            const float* srcV = &g_V[(size_t)(((bb * NH_ + h) * T_) + s0 + sl) * DH_ + dq4 * 4];
            cp16(smem_u32 + (unsigned int)(VS_OFF + bi * VBUF + (bb * TS + sl) * VSTR + dq4 * 4) * 4, srcV);
            int sl2 = sbb & 15, tq2 = sbb >> 4;
            const float* srcR = &rel[((size_t)(t0 + tq2) * T_ + (s0 + sl2)) * D_ + h * DH_ + dq4 * 4];
            cp16(smem_u32 + (unsigned int)(RS_OFF + bi * RBUF + (tq2 * TS + sl2) * KSTR + dq4 * 4) * 4, srcR);
        }
    };

    // Prologue: tiles 0 and 1 in flight
    issue_tile(0, 0);  cp_commit();
    issue_tile(TS, 1); cp_commit();

    // Q tile: 64 rows x 64 d (plain loads, covered by first barrier)
#pragma unroll
    for (int p = 0; p < 2; p++) {
        int f = tid + p * 512;
        int r = f >> 4, q4 = f & 15;
        int b = r >> 3, tq = r & 7;
        const float4* src = (const float4*)&g_Q[(size_t)(((b * NH_ + h) * T_) + t0 + tq) * DH_];
        ((float4*)&Qs[r * 64])[q4] = src[q4];
    }

    float ctx[8];
#pragma unroll
    for (int i = 0; i < 8; i++) ctx[i] = 0.f;
    float m_run = -1e30f, l_run = 0.f;

    for (int it = 0; it < T_ / TS; it++) {
        const int bi = it & 1;
        if (it == T_ / TS - 1) cp_wait<0>(); else cp_wait<1>();
        __syncthreads();                 // tile 'it' visible to all

        // ---- scores: 2 per thread (sl = lane8, lane8+8), fp32 ----
        float a0k = 0.f, a0r = 0.f, a1k = 0.f, a1r = 0.f;
        {
            const float* qp = &Qs[row * 64];
            const float* k0 = &Ks[bi * KBUF + (b_r * TS + lane8) * KSTR];
            const float* k1 = k0 + 8 * KSTR;
            const float* r0 = &Rs[bi * RBUF + (tq_r * TS + lane8) * KSTR];
            const float* r1 = r0 + 8 * KSTR;
#pragma unroll
            for (int k = 0; k < 64; k += 4) {
                float4 q  = *(const float4*)(qp + k);
                float4 ka = *(const float4*)(k0 + k);
                float4 kb = *(const float4*)(k1 + k);
                float4 ra = *(const float4*)(r0 + k);
                float4 rb = *(const float4*)(r1 + k);
                a0k += q.x * ka.x; a0k += q.y * ka.y; a0k += q.z * ka.z; a0k += q.w * ka.w;
                a0r += q.x * ra.x; a0r += q.y * ra.y; a0r += q.z * ra.z; a0r += q.w * ra.w;
                a1k += q.x * kb.x; a1k += q.y * kb.y; a1k += q.z * kb.z; a1k += q.w * kb.w;
                a1r += q.x * rb.x; a1r += q.y * rb.y; a1r += q.z * rb.z; a1r += q.w * rb.w;
            }
        }
        float s0 = (a0k + a0r) * 0.125f;
        float s1 = (a1k + a1r) * 0.125f;

        // ---- online softmax via shuffles within the 8-thread row group ----
        float mx = fmaxf(s0, s1);
        mx = fmaxf(mx, __shfl_xor_sync(0xffffffffu, mx, 1, 8));
        mx = fmaxf(mx, __shfl_xor_sync(0xffffffffu, mx, 2, 8));
        mx = fmaxf(mx, __shfl_xor_sync(0xffffffffu, mx, 4, 8));
        float m_new = fmaxf(m_run, mx);
        float scale = __expf(m_run - m_new);
        float p0 = __expf(s0 - m_new);
        float p1 = __expf(s1 - m_new);
        float ls = p0 + p1;
        ls += __shfl_xor_sync(0xffffffffu, ls, 1, 8);
        ls += __shfl_xor_sync(0xffffffffu, ls, 2, 8);
        ls += __shfl_xor_sync(0xffffffffu, ls, 4, 8);
        l_run = l_run * scale + ls;
        m_run = m_new;

        // ---- AV: thread owns d = lane8*4..+3 and 32+lane8*4..+3 ----
#pragma unroll
        for (int i = 0; i < 8; i++) ctx[i] *= scale;
        {
            const float* vbase = &Vs[bi * VBUF + (b_r * TS) * VSTR + lane8 * 4];
#pragma unroll
            for (int sl = 0; sl < TS; sl++) {
                float p = (sl < 8) ? __shfl_sync(0xffffffffu, p0, sl, 8)
                                   : __shfl_sync(0xffffffffu, p1, sl - 8, 8);
                float4 v0 = *(const float4*)(vbase + sl * VSTR);
                float4 v1 = *(const float4*)(vbase + sl * VSTR + 32);
                ctx[0] += p * v0.x; ctx[1] += p * v0.y;
                ctx[2] += p * v0.z; ctx[3] += p * v0.w;
                ctx[4] += p * v1.x; ctx[5] += p * v1.y;
                ctx[6] += p * v1.z; ctx[7] += p * v1.w;
            }
        }

        __syncthreads();                 // buffer bi fully consumed
        if (it + 2 < T_ / TS) issue_tile((it + 2) * TS, bi);
        cp_commit();                     // uniform group count
    }

    // Finalize: divide by l, write g_ctx[b][t][h*64 + d]
    const float inv = 1.0f / l_run;
    float* dst = &g_ctx[((size_t)(b_r * T_ + t0 + tq_r)) * D_ + h * DH_ + lane8 * 4];
    float4 o0 = make_float4(ctx[0] * inv, ctx[1] * inv, ctx[2] * inv, ctx[3] * inv);
    float4 o1 = make_float4(ctx[4] * inv, ctx[5] * inv, ctx[6] * inv, ctx[7] * inv);
    *(float4*)dst = o0;
    *(float4*)(dst + 32) = o1;
}

// ---------------------------------------------------------------------------
extern "C" void kernel_launch(void* const* d_in, const int* in_sizes, int n_in,
                              void* d_out, int out_size) {
    const float* x   = (const float*)d_in[0];
    const float* rel = (const float*)d_in[1];
    const float* Wq  = (const float*)d_in[2];
    const float* bq  = (const float*)d_in[3];
    const float* Wk  = (const float*)d_in[4];
    const float* bk  = (const float*)d_in[5];
    const float* Wv  = (const float*)d_in[6];
    const float* bv  = (const float*)d_in[7];
    const float* Wo  = (const float*)d_in[8];
    const float* bo  = (const float*)d_in[9];
    float* out = (float*)d_out;

    cudaFuncSetAttribute(attn_kernel, cudaFuncAttributeMaxDynamicSharedMemorySize, SMEM_BYTES);

    dim3 gg(64, 8);
    gemm_k<0><<<gg, 256>>>(x, Wq, bq, nullptr);
    gemm_k<1><<<gg, 256>>>(x, Wk, bk, nullptr);
    gemm_k<2><<<gg, 256>>>(x, Wv, bv, nullptr);

    attn_kernel<<<dim3(T_ / TQ, NH_), 512, SMEM_BYTES>>>(rel);

    gemm_k<3><<<gg, 256>>>(nullptr, Wo, bo, out);
}

// round 5
// speedup vs baseline: 3.1383x; 1.0592x over previous
#include <cuda_runtime.h>
#include <cuda_bf16.h>
#include <cstdint>
#include <math.h>

#define B_   8
#define T_   512
#define D_   512
#define NH_  8
#define DH_  64

#define TQ 8     // query rows per attention block
#define TS 16    // s-tile

// Scratch (static device arrays; no allocations allowed)
__device__ float g_Q[B_ * NH_ * T_ * DH_];   // [b][h][t][d]
__device__ float g_K[B_ * NH_ * T_ * DH_];
__device__ float g_V[B_ * NH_ * T_ * DH_];
__device__ float g_ctx[B_ * T_ * D_];        // [b][t][h*64+d]

// ---------------------------------------------------------------------------
// cp.async helpers
// ---------------------------------------------------------------------------
__device__ __forceinline__ void cp16(unsigned int smem_addr, const void* gptr) {
    asm volatile("cp.async.cg.shared.global [%0], [%1], 16;\n"
                 :: "r"(smem_addr), "l"(gptr));
}
__device__ __forceinline__ void cp_commit() {
    asm volatile("cp.async.commit_group;\n");
}
template <int N>
__device__ __forceinline__ void cp_wait() {
    asm volatile("cp.async.wait_group %0;\n" :: "n"(N));
}

// ---------------------------------------------------------------------------
// GEMM: C[i,j] = sum_k A[i,k] * W[j,k] + bias[j]
// ---------------------------------------------------------------------------
template <int DST>
__global__ __launch_bounds__(256) void gemm_k(const float* __restrict__ A,
                                              const float* __restrict__ W,
                                              const float* __restrict__ bias,
                                              float* __restrict__ Cout) {
    __shared__ float Xs[16][68];
    __shared__ float Ws[16][68];

    const float* Ap = (DST == 3) ? (const float*)g_ctx : A;

    const int i0 = blockIdx.x * 64;
    const int j0 = blockIdx.y * 64;
    const int tid = threadIdx.x;
    const int tx = tid & 15;
    const int ty = tid >> 4;
    const int li = tid >> 2;
    const int lq = tid & 3;

    float acc[4][4];
#pragma unroll
    for (int a = 0; a < 4; a++)
#pragma unroll
        for (int b = 0; b < 4; b++) acc[a][b] = 0.f;

    for (int kk = 0; kk < 512; kk += 16) {
        __syncthreads();
        float4 xa = *(const float4*)&Ap[(size_t)(i0 + li) * 512 + kk + lq * 4];
        float4 wa = *(const float4*)&W[(size_t)(j0 + li) * 512 + kk + lq * 4];
        Xs[lq * 4 + 0][li] = xa.x; Xs[lq * 4 + 1][li] = xa.y;
        Xs[lq * 4 + 2][li] = xa.z; Xs[lq * 4 + 3][li] = xa.w;
        Ws[lq * 4 + 0][li] = wa.x; Ws[lq * 4 + 1][li] = wa.y;
        Ws[lq * 4 + 2][li] = wa.z; Ws[lq * 4 + 3][li] = wa.w;
        __syncthreads();

#pragma unroll
        for (int k = 0; k < 16; k++) {
            float4 a = *(const float4*)&Xs[k][tx * 4];
            float4 b = *(const float4*)&Ws[k][ty * 4];
            acc[0][0] += a.x * b.x; acc[0][1] += a.x * b.y; acc[0][2] += a.x * b.z; acc[0][3] += a.x * b.w;
            acc[1][0] += a.y * b.x; acc[1][1] += a.y * b.y; acc[1][2] += a.y * b.z; acc[1][3] += a.y * b.w;
            acc[2][0] += a.z * b.x; acc[2][1] += a.z * b.y; acc[2][2] += a.z * b.z; acc[2][3] += a.z * b.w;
            acc[3][0] += a.w * b.x; acc[3][1] += a.w * b.y; acc[3][2] += a.w * b.z; acc[3][3] += a.w * b.w;
        }
    }

#pragma unroll
    for (int ii = 0; ii < 4; ii++) {
        const int i = i0 + tx * 4 + ii;
#pragma unroll
        for (int jj = 0; jj < 4; jj++) {
            const int j = j0 + ty * 4 + jj;
            float v = acc[ii][jj] + bias[j];
            if (DST == 3) {
                Cout[(size_t)i * 512 + j] = v;
            } else {
                const int b = i >> 9, t = i & 511;
                const int h = j >> 6, dh = j & 63;
                float* dst = (DST == 0) ? g_Q : (DST == 1) ? g_K : g_V;
                dst[(((b * NH_ + h) * T_) + t) * DH_ + dh] = v;
            }
        }
    }
}

// ---------------------------------------------------------------------------
// Attention v2: conflict-free smem + cp.async double buffering + shfl softmax
// Block: (head h, 8-query tile t0), covers all 8 batches. 512 threads.
// thread: row = tid>>3 (b*8+tq), lane8 = tid&7 (score: sl group / AV: d seg)
// ---------------------------------------------------------------------------
#define KSTR 68                         // K/R row stride (floats), bank-spread
#define VSTR 64
#define QS_OFF  0
#define KS_OFF  (QS_OFF + 64 * 64)                  // 4096
#define KBUF    (B_ * TS * KSTR)                    // 8704
#define VS_OFF  (KS_OFF + 2 * KBUF)                 // 21504
#define VBUF    (B_ * TS * VSTR)                    // 8192
#define RS_OFF  (VS_OFF + 2 * VBUF)                 // 37888
#define RBUF    (TQ * TS * KSTR)                    // 8704
#define SMEM_FLOATS (RS_OFF + 2 * RBUF)             // 55296
#define SMEM_BYTES  (SMEM_FLOATS * 4)               // 221184

__global__ __launch_bounds__(512, 1) void attn_kernel(const float* __restrict__ rel) {
    const int h = blockIdx.y;
    const int t0 = blockIdx.x * TQ;

    extern __shared__ float sm[];
    float* Qs = sm + QS_OFF;
    float* Ks = sm + KS_OFF;
    float* Vs = sm + VS_OFF;
    float* Rs = sm + RS_OFF;

    const int tid = threadIdx.x;
    const int row   = tid >> 3;     // 0..63 (= b*8 + tq)
    const int lane8 = tid & 7;
    const int b_r   = row >> 3;
    const int tq_r  = row & 7;

    const unsigned int smem_u32 = (unsigned int)__cvta_generic_to_shared(sm);

    // Issue loads for tile starting at s0 into buffer bi (12 x 16B per thread)
    auto issue_tile = [&](int s0, int bi) {
#pragma unroll
        for (int p = 0; p < 4; p++) {
            int f  = tid + p * 512;
            int dq4 = f & 15;
            int sbb = f >> 4;                  // 0..127
            int bb = sbb & 7, sl = sbb >> 3;
            const float* srcK = &g_K[(size_t)(((bb * NH_ + h) * T_) + s0 + sl) * DH_ + dq4 * 4];
            cp16(smem_u32 + (unsigned int)(KS_OFF + bi * KBUF + (bb * TS + sl) * KSTR + dq4 * 4) * 4, srcK);
            const float* srcV = &g_V[(size_t)(((bb * NH_ + h) * T_) + s0 + sl) * DH_ + dq4 * 4];
            cp16(smem_u32 + (unsigned int)(VS_OFF + bi * VBUF + (bb * TS + sl) * VSTR + dq4 * 4) * 4, srcV);
            int sl2 = sbb & 15, tq2 = sbb >> 4;
            const float* srcR = &rel[((size_t)(t0 + tq2) * T_ + (s0 + sl2)) * D_ + h * DH_ + dq4 * 4];
            cp16(smem_u32 + (unsigned int)(RS_OFF + bi * RBUF + (tq2 * TS + sl2) * KSTR + dq4 * 4) * 4, srcR);
        }
    };

    // Prologue: tiles 0 and 1 in flight
    issue_tile(0, 0);  cp_commit();
    issue_tile(TS, 1); cp_commit();

    // Q tile: 64 rows x 64 d (plain loads, covered by first barrier)
#pragma unroll
    for (int p = 0; p < 2; p++) {
        int f = tid + p * 512;
        int r = f >> 4, q4 = f & 15;
        int b = r >> 3, tq = r & 7;
        const float4* src = (const float4*)&g_Q[(size_t)(((b * NH_ + h) * T_) + t0 + tq) * DH_];
        ((float4*)&Qs[r * 64])[q4] = src[q4];
    }

    float ctx[8];
#pragma unroll
    for (int i = 0; i < 8; i++) ctx[i] = 0.f;
    float m_run = -1e30f, l_run = 0.f;

    for (int it = 0; it < T_ / TS; it++) {
        const int bi = it & 1;
        if (it == T_ / TS - 1) cp_wait<0>(); else cp_wait<1>();
        __syncthreads();                 // tile 'it' visible to all

        // ---- scores: 2 per thread (sl = lane8, lane8+8), fp32 ----
        float a0k = 0.f, a0r = 0.f, a1k = 0.f, a1r = 0.f;
        {
            const float* qp = &Qs[row * 64];
            const float* k0 = &Ks[bi * KBUF + (b_r * TS + lane8) * KSTR];
            const float* k1 = k0 + 8 * KSTR;
            const float* r0 = &Rs[bi * RBUF + (tq_r * TS + lane8) * KSTR];
            const float* r1 = r0 + 8 * KSTR;
#pragma unroll
            for (int k = 0; k < 64; k += 4) {
                float4 q  = *(const float4*)(qp + k);
                float4 ka = *(const float4*)(k0 + k);
                float4 kb = *(const float4*)(k1 + k);
                float4 ra = *(const float4*)(r0 + k);
                float4 rb = *(const float4*)(r1 + k);
                a0k += q.x * ka.x; a0k += q.y * ka.y; a0k += q.z * ka.z; a0k += q.w * ka.w;
                a0r += q.x * ra.x; a0r += q.y * ra.y; a0r += q.z * ra.z; a0r += q.w * ra.w;
                a1k += q.x * kb.x; a1k += q.y * kb.y; a1k += q.z * kb.z; a1k += q.w * kb.w;
                a1r += q.x * rb.x; a1r += q.y * rb.y; a1r += q.z * rb.z; a1r += q.w * rb.w;
            }
        }
        float s0 = (a0k + a0r) * 0.125f;
        float s1 = (a1k + a1r) * 0.125f;

        // ---- online softmax via shuffles within the 8-thread row group ----
        float mx = fmaxf(s0, s1);
        mx = fmaxf(mx, __shfl_xor_sync(0xffffffffu, mx, 1, 8));
        mx = fmaxf(mx, __shfl_xor_sync(0xffffffffu, mx, 2, 8));
        mx = fmaxf(mx, __shfl_xor_sync(0xffffffffu, mx, 4, 8));
        float m_new = fmaxf(m_run, mx);
        float scale = __expf(m_run - m_new);
        float p0 = __expf(s0 - m_new);
        float p1 = __expf(s1 - m_new);
        float ls = p0 + p1;
        ls += __shfl_xor_sync(0xffffffffu, ls, 1, 8);
        ls += __shfl_xor_sync(0xffffffffu, ls, 2, 8);
        ls += __shfl_xor_sync(0xffffffffu, ls, 4, 8);
        l_run = l_run * scale + ls;
        m_run = m_new;

        // ---- AV: thread owns d = lane8*4..+3 and 32+lane8*4..+3 ----
#pragma unroll
        for (int i = 0; i < 8; i++) ctx[i] *= scale;
        {
            const float* vbase = &Vs[bi * VBUF + (b_r * TS) * VSTR + lane8 * 4];
#pragma unroll
            for (int sl = 0; sl < TS; sl++) {
                float p = (sl < 8) ? __shfl_sync(0xffffffffu, p0, sl, 8)
                                   : __shfl_sync(0xffffffffu, p1, sl - 8, 8);
                float4 v0 = *(const float4*)(vbase + sl * VSTR);
                float4 v1 = *(const float4*)(vbase + sl * VSTR + 32);
                ctx[0] += p * v0.x; ctx[1] += p * v0.y;
                ctx[2] += p * v0.z; ctx[3] += p * v0.w;
                ctx[4] += p * v1.x; ctx[5] += p * v1.y;
                ctx[6] += p * v1.z; ctx[7] += p * v1.w;
            }
        }

        __syncthreads();                 // buffer bi fully consumed
        if (it + 2 < T_ / TS) issue_tile((it + 2) * TS, bi);
        cp_commit();                     // uniform group count
    }

    // Finalize: divide by l, write g_ctx[b][t][h*64 + d]
    const float inv = 1.0f / l_run;
    float* dst = &g_ctx[((size_t)(b_r * T_ + t0 + tq_r)) * D_ + h * DH_ + lane8 * 4];
    float4 o0 = make_float4(ctx[0] * inv, ctx[1] * inv, ctx[2] * inv, ctx[3] * inv);
    float4 o1 = make_float4(ctx[4] * inv, ctx[5] * inv, ctx[6] * inv, ctx[7] * inv);
    *(float4*)dst = o0;
    *(float4*)(dst + 32) = o1;
}

// ---------------------------------------------------------------------------
extern "C" void kernel_launch(void* const* d_in, const int* in_sizes, int n_in,
                              void* d_out, int out_size) {
    const float* x   = (const float*)d_in[0];
    const float* rel = (const float*)d_in[1];
    const float* Wq  = (const float*)d_in[2];
    const float* bq  = (const float*)d_in[3];
    const float* Wk  = (const float*)d_in[4];
    const float* bk  = (const float*)d_in[5];
    const float* Wv  = (const float*)d_in[6];
    const float* bv  = (const float*)d_in[7];
    const float* Wo  = (const float*)d_in[8];
    const float* bo  = (const float*)d_in[9];
    float* out = (float*)d_out;

    cudaFuncSetAttribute(attn_kernel, cudaFuncAttributeMaxDynamicSharedMemorySize, SMEM_BYTES);

    dim3 gg(64, 8);
    gemm_k<0><<<gg, 256>>>(x, Wq, bq, nullptr);
    gemm_k<1><<<gg, 256>>>(x, Wk, bk, nullptr);
    gemm_k<2><<<gg, 256>>>(x, Wv, bv, nullptr);

    attn_kernel<<<dim3(T_ / TQ, NH_), 512, SMEM_BYTES>>>(rel);

    gemm_k<3><<<gg, 256>>>(nullptr, Wo, bo, out);
}

// round 6
// speedup vs baseline: 5.0409x; 1.6062x over previous
#include <cuda_runtime.h>
#include <cuda_bf16.h>
#include <cstdint>
#include <math.h>

#define B_   8
#define T_   512
#define D_   512
#define NH_  8
#define DH_  64

#define PLANE_ELEMS (B_ * NH_ * T_ * DH_)
__device__ __nv_bfloat16 g_Qh[PLANE_ELEMS], g_Ql[PLANE_ELEMS];   // [b][h][t][d], pre-scaled 1/8
__device__ __nv_bfloat16 g_Kh[PLANE_ELEMS], g_Kl[PLANE_ELEMS];   // [b][h][t][d]
__device__ __nv_bfloat16 g_VTh[PLANE_ELEMS], g_VTl[PLANE_ELEMS]; // [b][h][d][t]
__device__ float g_pos[NH_ * T_ * B_ * T_];                      // [h][t][b][s]
__device__ float g_ctx[B_ * T_ * D_];                            // [b][t][h*64+d]

// ---------------- helpers ----------------
__device__ __forceinline__ void cp16(unsigned smem_addr, const void* g) {
    asm volatile("cp.async.cg.shared.global [%0], [%1], 16;\n" :: "r"(smem_addr), "l"(g));
}
__device__ __forceinline__ void cp_commit() { asm volatile("cp.async.commit_group;\n"); }
template <int N> __device__ __forceinline__ void cp_wait() {
    asm volatile("cp.async.wait_group %0;\n" :: "n"(N));
}
__device__ __forceinline__ unsigned pack2(__nv_bfloat16 x, __nv_bfloat16 y) {
    __nv_bfloat162 t; t.x = x; t.y = y;
    return *reinterpret_cast<unsigned*>(&t);
}
__device__ __forceinline__ void split2(float x, float y, unsigned& hi, unsigned& lo) {
    __nv_bfloat16 xh = __float2bfloat16(x), yh = __float2bfloat16(y);
    hi = pack2(xh, yh);
    lo = pack2(__float2bfloat16(x - __bfloat162float(xh)),
               __float2bfloat16(y - __bfloat162float(yh)));
}
__device__ __forceinline__ void mma16816(float& c0, float& c1, float& c2, float& c3,
                                         unsigned a0, unsigned a1, unsigned a2, unsigned a3,
                                         unsigned b0, unsigned b1) {
    asm volatile("mma.sync.aligned.m16n8k16.row.col.f32.bf16.bf16.f32 "
                 "{%0,%1,%2,%3},{%4,%5,%6,%7},{%8,%9},{%0,%1,%2,%3};\n"
                 : "+f"(c0), "+f"(c1), "+f"(c2), "+f"(c3)
                 : "r"(a0), "r"(a1), "r"(a2), "r"(a3), "r"(b0), "r"(b1));
}

// ---------------------------------------------------------------------------
// GEMM: C[i,j] = sum_k A[i,k]*W[j,k] + bias[j]
// DST 0: Q planes (scaled 1/8)  1: K planes  2: V^T planes  3: fp32 out
// ---------------------------------------------------------------------------
template <int DST>
__global__ __launch_bounds__(256) void gemm_k(const float* __restrict__ A,
                                              const float* __restrict__ W,
                                              const float* __restrict__ bias,
                                              float* __restrict__ Cout) {
    __shared__ float Xs[16][68];
    __shared__ float Ws[16][68];
    const float* Ap = (DST == 3) ? (const float*)g_ctx : A;
    const int i0 = blockIdx.x * 64, j0 = blockIdx.y * 64;
    const int tid = threadIdx.x;
    const int tx = tid & 15, ty = tid >> 4;
    const int li = tid >> 2, lq = tid & 3;

    float acc[4][4];
#pragma unroll
    for (int a = 0; a < 4; a++)
#pragma unroll
        for (int b = 0; b < 4; b++) acc[a][b] = 0.f;

    for (int kk = 0; kk < 512; kk += 16) {
        __syncthreads();
        float4 xa = *(const float4*)&Ap[(size_t)(i0 + li) * 512 + kk + lq * 4];
        float4 wa = *(const float4*)&W[(size_t)(j0 + li) * 512 + kk + lq * 4];
        Xs[lq*4+0][li]=xa.x; Xs[lq*4+1][li]=xa.y; Xs[lq*4+2][li]=xa.z; Xs[lq*4+3][li]=xa.w;
        Ws[lq*4+0][li]=wa.x; Ws[lq*4+1][li]=wa.y; Ws[lq*4+2][li]=wa.z; Ws[lq*4+3][li]=wa.w;
        __syncthreads();
#pragma unroll
        for (int k = 0; k < 16; k++) {
            float4 a = *(const float4*)&Xs[k][tx*4];
            float4 b = *(const float4*)&Ws[k][ty*4];
            acc[0][0]+=a.x*b.x; acc[0][1]+=a.x*b.y; acc[0][2]+=a.x*b.z; acc[0][3]+=a.x*b.w;
            acc[1][0]+=a.y*b.x; acc[1][1]+=a.y*b.y; acc[1][2]+=a.y*b.z; acc[1][3]+=a.y*b.w;
            acc[2][0]+=a.z*b.x; acc[2][1]+=a.z*b.y; acc[2][2]+=a.z*b.z; acc[2][3]+=a.z*b.w;
            acc[3][0]+=a.w*b.x; acc[3][1]+=a.w*b.y; acc[3][2]+=a.w*b.z; acc[3][3]+=a.w*b.w;
        }
    }

#pragma unroll
    for (int ii = 0; ii < 4; ii++) {
        const int i = i0 + tx*4 + ii;
#pragma unroll
        for (int jj = 0; jj < 4; jj++) {
            const int j = j0 + ty*4 + jj;
            float v = acc[ii][jj] + bias[j];
            if (DST == 3) { Cout[(size_t)i * 512 + j] = v; continue; }
            const int b = i >> 9, t = i & 511;
            const int hh = j >> 6, dh = j & 63;
            if (DST == 0) v *= 0.125f;
            __nv_bfloat16 hi = __float2bfloat16(v);
            __nv_bfloat16 lo = __float2bfloat16(v - __bfloat162float(hi));
            if (DST == 0) {
                size_t o = ((size_t)(b*NH_+hh)*T_ + t)*64 + dh;
                g_Qh[o] = hi; g_Ql[o] = lo;
            } else if (DST == 1) {
                size_t o = ((size_t)(b*NH_+hh)*T_ + t)*64 + dh;
                g_Kh[o] = hi; g_Kl[o] = lo;
            } else {
                size_t o = ((size_t)(b*NH_+hh)*64 + dh)*T_ + t;
                g_VTh[o] = hi; g_VTl[o] = lo;
            }
        }
    }
}

// ---------------------------------------------------------------------------
// pos[h][t][b][s] = Q[b,h,t,:] . rel[t,s,:]   (Q pre-scaled by 1/8)
// CTA = (t, h), 4 warps; warp does 16-s strips. MMA: M=s(16), N=b(8), K=64.
// A = rel rows (fp32 -> split on the fly), B = Q columns across b.
// ---------------------------------------------------------------------------
__global__ __launch_bounds__(128) void pos_kernel(const float* __restrict__ rel) {
    const int t = blockIdx.x, h = blockIdx.y;
    const int tid = threadIdx.x;
    const int wid = tid >> 5, lane = tid & 31;
    const int grp = lane >> 2, q = lane & 3;

    // B fragments (Q_t): b0 = Q[b=grp][d=kk*16+2q,+1], b1 = d+8
    unsigned Bh[4][2], Bl[4][2];
#pragma unroll
    for (int kk = 0; kk < 4; kk++) {
        size_t base = ((size_t)(grp*NH_+h)*T_ + t)*64 + kk*16 + 2*q;
        Bh[kk][0] = *(const unsigned*)&g_Qh[base];
        Bh[kk][1] = *(const unsigned*)&g_Qh[base + 8];
        Bl[kk][0] = *(const unsigned*)&g_Ql[base];
        Bl[kk][1] = *(const unsigned*)&g_Ql[base + 8];
    }

    for (int it = 0; it < 8; it++) {
        const int s0 = it * 64 + wid * 16;
        float c0 = 0.f, c1 = 0.f, c2 = 0.f, c3 = 0.f;
#pragma unroll
        for (int kk = 0; kk < 4; kk++) {
            const float* r0 = rel + ((size_t)t*T_ + s0 + grp)*D_ + h*64 + kk*16 + 2*q;
            const float* r1 = r0 + 8 * D_;     // s+8
            float2 rA0 = *(const float2*)r0;
            float2 rA2 = *(const float2*)(r0 + 8);
            float2 rA1 = *(const float2*)r1;
            float2 rA3 = *(const float2*)(r1 + 8);
            unsigned ah0, al0, ah1, al1, ah2, al2, ah3, al3;
            split2(rA0.x, rA0.y, ah0, al0);
            split2(rA1.x, rA1.y, ah1, al1);
            split2(rA2.x, rA2.y, ah2, al2);
            split2(rA3.x, rA3.y, ah3, al3);
            mma16816(c0,c1,c2,c3, ah0,ah1,ah2,ah3, Bh[kk][0], Bh[kk][1]);
            mma16816(c0,c1,c2,c3, ah0,ah1,ah2,ah3, Bl[kk][0], Bl[kk][1]);
            mma16816(c0,c1,c2,c3, al0,al1,al2,al3, Bh[kk][0], Bh[kk][1]);
        }
        size_t o = ((size_t)h*T_ + t) * B_;
        g_pos[(o + 2*q    )*T_ + s0 + grp    ] = c0;
        g_pos[(o + 2*q + 1)*T_ + s0 + grp    ] = c1;
        g_pos[(o + 2*q    )*T_ + s0 + grp + 8] = c2;
        g_pos[(o + 2*q + 1)*T_ + s0 + grp + 8] = c3;
    }
}

// ---------------------------------------------------------------------------
// FA2 attention with bias. CTA = (h, 16-t tile), warp = batch b. s-tiles of 16.
// smem: K [buf][pl][b][s] rows 144B; VT [buf][pl][b][d] rows 48B; pos [buf][b][t][16]
// ---------------------------------------------------------------------------
#define KS_B   0
#define KBUF_B 36864
#define KPL_B  18432
#define VS_B   73728
#define VBUF_B 49152
#define VPL_B  24576
#define PS_B   172032
#define PBUF_B 8192
#define SMEM_BYTES 188416

__global__ __launch_bounds__(256, 1) void attn_mma() {
    const int h  = blockIdx.y;
    const int t0 = blockIdx.x * 16;
    extern __shared__ char sm[];
    const unsigned sb = (unsigned)__cvta_generic_to_shared(sm);

    const int tid = threadIdx.x;
    const int wid = tid >> 5;            // batch b
    const int lane = tid & 31;
    const int grp = lane >> 2, q = lane & 3;

    // Q A-fragments from global (m=t, k=d)
    unsigned QAh[4][4], QAl[4][4];
#pragma unroll
    for (int kk = 0; kk < 4; kk++) {
        size_t base = ((size_t)(wid*NH_+h)*T_ + t0 + grp)*64 + kk*16 + 2*q;
        QAh[kk][0] = *(const unsigned*)&g_Qh[base];
        QAh[kk][1] = *(const unsigned*)&g_Qh[base + 8*64];
        QAh[kk][2] = *(const unsigned*)&g_Qh[base + 8];
        QAh[kk][3] = *(const unsigned*)&g_Qh[base + 8*64 + 8];
        QAl[kk][0] = *(const unsigned*)&g_Ql[base];
        QAl[kk][1] = *(const unsigned*)&g_Ql[base + 8*64];
        QAl[kk][2] = *(const unsigned*)&g_Ql[base + 8];
        QAl[kk][3] = *(const unsigned*)&g_Ql[base + 8*64 + 8];
    }

    auto issue_tile = [&](int s0, int buf) {
        for (int i = tid; i < 2048; i += 256) {            // K
            int q4 = i & 7, row = i >> 3;
            int s = row & 15, b = (row >> 4) & 7, pl = row >> 7;
            const __nv_bfloat16* src =
                (pl ? g_Kl : g_Kh) + ((size_t)(b*NH_+h)*T_ + s0 + s)*64 + q4*8;
            cp16(sb + KS_B + buf*KBUF_B + pl*KPL_B + (b*16 + s)*144 + q4*16, src);
        }
        for (int i = tid; i < 2048; i += 256) {            // V^T
            int q4 = i & 1, row = i >> 1;
            int d = row & 63, b = (row >> 6) & 7, pl = row >> 9;
            const __nv_bfloat16* src =
                (pl ? g_VTl : g_VTh) + ((size_t)(b*NH_+h)*64 + d)*T_ + s0 + q4*8;
            cp16(sb + VS_B + buf*VBUF_B + pl*VPL_B + (b*64 + d)*48 + q4*16, src);
        }
        for (int i = tid; i < 512; i += 256) {             // pos bias
            int q4 = i & 3, row = i >> 2;
            int t = row & 15, b = row >> 4;
            const float* src = g_pos + ((size_t)(h*T_ + t0 + t)*B_ + b)*T_ + s0 + q4*4;
            cp16(sb + PS_B + buf*PBUF_B + (b*16 + t)*64 + q4*16, src);
        }
    };

    issue_tile(0, 0);  cp_commit();
    issue_tile(16, 1); cp_commit();

    float ctx[8][4];
#pragma unroll
    for (int nt = 0; nt < 8; nt++)
#pragma unroll
        for (int i = 0; i < 4; i++) ctx[nt][i] = 0.f;
    float m_a = -1e30f, m_b = -1e30f, l_a = 0.f, l_b = 0.f;

    for (int it = 0; it < 32; it++) {
        const int buf = it & 1;
        if (it == 31) cp_wait<0>(); else cp_wait<1>();
        __syncthreads();

        // ---- content scores, C initialized with pos bias ----
        float sg[2][4];
        const float* pp = (const float*)(sm + PS_B + buf*PBUF_B) + (wid*16 + grp)*16;
#pragma unroll
        for (int ng = 0; ng < 2; ng++) {
            float2 pa = *(const float2*)(pp + ng*8 + 2*q);
            float2 pb = *(const float2*)(pp + 8*16 + ng*8 + 2*q);
            float c0 = pa.x, c1 = pa.y, c2 = pb.x, c3 = pb.y;
#pragma unroll
            for (int kk = 0; kk < 4; kk++) {
                const char* kp = sm + KS_B + buf*KBUF_B + (wid*16 + ng*8 + grp)*144 + kk*32 + q*4;
                unsigned bh0 = *(const unsigned*)kp;
                unsigned bh1 = *(const unsigned*)(kp + 16);
                unsigned bl0 = *(const unsigned*)(kp + KPL_B);
                unsigned bl1 = *(const unsigned*)(kp + KPL_B + 16);
                mma16816(c0,c1,c2,c3, QAh[kk][0],QAh[kk][1],QAh[kk][2],QAh[kk][3], bh0, bh1);
                mma16816(c0,c1,c2,c3, QAh[kk][0],QAh[kk][1],QAh[kk][2],QAh[kk][3], bl0, bl1);
                mma16816(c0,c1,c2,c3, QAl[kk][0],QAl[kk][1],QAl[kk][2],QAl[kk][3], bh0, bh1);
            }
            sg[ng][0] = c0; sg[ng][1] = c1; sg[ng][2] = c2; sg[ng][3] = c3;
        }

        // ---- online softmax (rows t=grp and t=grp+8; reduce over 4 q-lanes) ----
        float ma = fmaxf(fmaxf(sg[0][0], sg[0][1]), fmaxf(sg[1][0], sg[1][1]));
        float mb = fmaxf(fmaxf(sg[0][2], sg[0][3]), fmaxf(sg[1][2], sg[1][3]));
        ma = fmaxf(ma, __shfl_xor_sync(0xffffffffu, ma, 1, 4));
        ma = fmaxf(ma, __shfl_xor_sync(0xffffffffu, ma, 2, 4));
        mb = fmaxf(mb, __shfl_xor_sync(0xffffffffu, mb, 1, 4));
        mb = fmaxf(mb, __shfl_xor_sync(0xffffffffu, mb, 2, 4));
        float mna = fmaxf(m_a, ma), mnb = fmaxf(m_b, mb);
        float sca = __expf(m_a - mna), scb = __expf(m_b - mnb);
        float pa0 = __expf(sg[0][0] - mna), pa1 = __expf(sg[0][1] - mna);
        float pa2 = __expf(sg[1][0] - mna), pa3 = __expf(sg[1][1] - mna);
        float pb0 = __expf(sg[0][2] - mnb), pb1 = __expf(sg[0][3] - mnb);
        float pb2 = __expf(sg[1][2] - mnb), pb3 = __expf(sg[1][3] - mnb);
        float la = pa0 + pa1 + pa2 + pa3;
        float lb = pb0 + pb1 + pb2 + pb3;
        la += __shfl_xor_sync(0xffffffffu, la, 1, 4);
        la += __shfl_xor_sync(0xffffffffu, la, 2, 4);
        lb += __shfl_xor_sync(0xffffffffu, lb, 1, 4);
        lb += __shfl_xor_sync(0xffffffffu, lb, 2, 4);
        l_a = l_a * sca + la; l_b = l_b * scb + lb;
        m_a = mna; m_b = mnb;

        // P -> A fragments (hi/lo)
        unsigned ah0, al0, ah1, al1, ah2, al2, ah3, al3;
        split2(pa0, pa1, ah0, al0);
        split2(pb0, pb1, ah1, al1);
        split2(pa2, pa3, ah2, al2);
        split2(pb2, pb3, ah3, al3);

#pragma unroll
        for (int nt = 0; nt < 8; nt++) {
            ctx[nt][0] *= sca; ctx[nt][1] *= sca;
            ctx[nt][2] *= scb; ctx[nt][3] *= scb;
        }
        // ---- AV ----
#pragma unroll
        for (int nt = 0; nt < 8; nt++) {
            const char* vp = sm + VS_B + buf*VBUF_B + (wid*64 + nt*8 + grp)*48 + q*4;
            unsigned bh0 = *(const unsigned*)vp;
            unsigned bh1 = *(const unsigned*)(vp + 16);
            unsigned bl0 = *(const unsigned*)(vp + VPL_B);
            unsigned bl1 = *(const unsigned*)(vp + VPL_B + 16);
            mma16816(ctx[nt][0],ctx[nt][1],ctx[nt][2],ctx[nt][3], ah0,ah1,ah2,ah3, bh0, bh1);
            mma16816(ctx[nt][0],ctx[nt][1],ctx[nt][2],ctx[nt][3], al0,al1,al2,al3, bh0, bh1);
            mma16816(ctx[nt][0],ctx[nt][1],ctx[nt][2],ctx[nt][3], ah0,ah1,ah2,ah3, bl0, bl1);
        }

        __syncthreads();
        if (it + 2 < 32) issue_tile((it + 2) * 16, buf);
        cp_commit();
    }

    const float inva = 1.0f / l_a, invb = 1.0f / l_b;
    float* o0 = g_ctx + ((size_t)wid*T_ + t0 + grp)*D_ + h*64 + 2*q;
    float* o1 = o0 + 8 * D_;
#pragma unroll
    for (int nt = 0; nt < 8; nt++) {
        *(float2*)(o0 + nt*8) = make_float2(ctx[nt][0]*inva, ctx[nt][1]*inva);
        *(float2*)(o1 + nt*8) = make_float2(ctx[nt][2]*invb, ctx[nt][3]*invb);
    }
}

// ---------------------------------------------------------------------------
extern "C" void kernel_launch(void* const* d_in, const int* in_sizes, int n_in,
                              void* d_out, int out_size) {
    const float* x   = (const float*)d_in[0];
    const float* rel = (const float*)d_in[1];
    const float* Wq  = (const float*)d_in[2];
    const float* bq  = (const float*)d_in[3];
    const float* Wk  = (const float*)d_in[4];
    const float* bk  = (const float*)d_in[5];
    const float* Wv  = (const float*)d_in[6];
    const float* bv  = (const float*)d_in[7];
    const float* Wo  = (const float*)d_in[8];
    const float* bo  = (const float*)d_in[9];
    float* out = (float*)d_out;

    cudaFuncSetAttribute(attn_mma, cudaFuncAttributeMaxDynamicSharedMemorySize, SMEM_BYTES);

    dim3 gg(64, 8);
    gemm_k<0><<<gg, 256>>>(x, Wq, bq, nullptr);
    gemm_k<1><<<gg, 256>>>(x, Wk, bk, nullptr);
    gemm_k<2><<<gg, 256>>>(x, Wv, bv, nullptr);

    pos_kernel<<<dim3(T_, NH_), 128>>>(rel);

    attn_mma<<<dim3(T_ / 16, NH_), 256, SMEM_BYTES>>>();

    gemm_k<3><<<gg, 256>>>(nullptr, Wo, bo, out);
}

// round 7
// speedup vs baseline: 7.2321x; 1.4347x over previous
#include <cuda_runtime.h>
#include <cuda_bf16.h>
#include <cstdint>
#include <math.h>

#define B_   8
#define T_   512
#define D_   512
#define NH_  8
#define DH_  64

#define PLANE_ELEMS (B_ * NH_ * T_ * DH_)
__device__ __nv_bfloat16 g_Qh[PLANE_ELEMS], g_Ql[PLANE_ELEMS];   // [b][h][t][d], pre-scaled 1/8
__device__ __nv_bfloat16 g_Kh[PLANE_ELEMS], g_Kl[PLANE_ELEMS];   // [b][h][t][d]
__device__ __nv_bfloat16 g_VTh[PLANE_ELEMS], g_VTl[PLANE_ELEMS]; // [b][h][d][t]
__device__ float g_pos[NH_ * T_ * B_ * T_];                      // [h][t][b][s]
__device__ float g_ctx[B_ * T_ * D_];                            // [b][t][h*64+d]

// ---------------- helpers ----------------
__device__ __forceinline__ void cp16(unsigned smem_addr, const void* g) {
    asm volatile("cp.async.cg.shared.global [%0], [%1], 16;\n" :: "r"(smem_addr), "l"(g));
}
__device__ __forceinline__ void cp_commit() { asm volatile("cp.async.commit_group;\n"); }
template <int N> __device__ __forceinline__ void cp_wait() {
    asm volatile("cp.async.wait_group %0;\n" :: "n"(N));
}
__device__ __forceinline__ unsigned pack2(__nv_bfloat16 x, __nv_bfloat16 y) {
    __nv_bfloat162 t; t.x = x; t.y = y;
    return *reinterpret_cast<unsigned*>(&t);
}
__device__ __forceinline__ void split2(float x, float y, unsigned& hi, unsigned& lo) {
    __nv_bfloat16 xh = __float2bfloat16(x), yh = __float2bfloat16(y);
    hi = pack2(xh, yh);
    lo = pack2(__float2bfloat16(x - __bfloat162float(xh)),
               __float2bfloat16(y - __bfloat162float(yh)));
}
__device__ __forceinline__ void mma16816(float& c0, float& c1, float& c2, float& c3,
                                         unsigned a0, unsigned a1, unsigned a2, unsigned a3,
                                         unsigned b0, unsigned b1) {
    asm volatile("mma.sync.aligned.m16n8k16.row.col.f32.bf16.bf16.f32 "
                 "{%0,%1,%2,%3},{%4,%5,%6,%7},{%8,%9},{%0,%1,%2,%3};\n"
                 : "+f"(c0), "+f"(c1), "+f"(c2), "+f"(c3)
                 : "r"(a0), "r"(a1), "r"(a2), "r"(a3), "r"(b0), "r"(b1));
}

// ---------------------------------------------------------------------------
// Tensor-core GEMM: C[i,j] = sum_k A[i,k]*W[j,k] + bias[j]
// A fp32 (x or g_ctx), split to bf16 hi/lo in registers at STS time.
// CTA: 128(i) x 64(j), 256 thr = 2x4 warps (warp tile 64x16), k-chunk 32.
// DST 0: Q planes (scaled 1/8)  1: K planes  2: V^T planes  3: fp32 out+bias
// ---------------------------------------------------------------------------
template <int DST>
__global__ __launch_bounds__(256) void mma_gemm(const float* __restrict__ A,
                                                const float* __restrict__ W,
                                                const float* __restrict__ bias,
                                                float* __restrict__ Cout) {
    __shared__ __nv_bfloat16 Ah[128][40], Al[128][40];
    __shared__ __nv_bfloat16 Wh[64][40],  Wl[64][40];

    const float* Ap = (DST == 3) ? (const float*)g_ctx : A;
    const int i0 = blockIdx.x * 128, j0 = blockIdx.y * 64;
    const int tid = threadIdx.x;
    const int wid = tid >> 5, lane = tid & 31;
    const int wm = wid & 1, wn = wid >> 1;       // warp tile: (wm*64, wn*16)
    const int grp = lane >> 2, q = lane & 3;

    // load mapping: A 128x32 fp32 (2 thr/row, 4 float4 each); W 64x32 (4 thr/row, 2 float4)
    const int ar = tid >> 1, ak = (tid & 1) * 16;
    const int wr = tid >> 2, wk = (tid & 3) * 8;

    float4 pa[4], pw[2];
    {
        const float* ab = Ap + (size_t)(i0 + ar) * 512 + ak;
        pa[0] = *(const float4*)(ab);      pa[1] = *(const float4*)(ab + 4);
        pa[2] = *(const float4*)(ab + 8);  pa[3] = *(const float4*)(ab + 12);
        const float* wb = W + (size_t)(j0 + wr) * 512 + wk;
        pw[0] = *(const float4*)(wb);      pw[1] = *(const float4*)(wb + 4);
    }

    float acc[4][2][4];
#pragma unroll
    for (int a = 0; a < 4; a++)
#pragma unroll
        for (int b = 0; b < 2; b++)
#pragma unroll
            for (int c = 0; c < 4; c++) acc[a][b][c] = 0.f;

    for (int kk = 0; kk < 16; kk++) {
        __syncthreads();
        // store prefetched chunk (split fp32 -> bf16 hi/lo)
#pragma unroll
        for (int t = 0; t < 4; t++) {
            unsigned h0, l0, h1, l1;
            split2(pa[t].x, pa[t].y, h0, l0);
            split2(pa[t].z, pa[t].w, h1, l1);
            *(unsigned*)&Ah[ar][ak + t * 4]     = h0;
            *(unsigned*)&Ah[ar][ak + t * 4 + 2] = h1;
            *(unsigned*)&Al[ar][ak + t * 4]     = l0;
            *(unsigned*)&Al[ar][ak + t * 4 + 2] = l1;
        }
#pragma unroll
        for (int t = 0; t < 2; t++) {
            unsigned h0, l0, h1, l1;
            split2(pw[t].x, pw[t].y, h0, l0);
            split2(pw[t].z, pw[t].w, h1, l1);
            *(unsigned*)&Wh[wr][wk + t * 4]     = h0;
            *(unsigned*)&Wh[wr][wk + t * 4 + 2] = h1;
            *(unsigned*)&Wl[wr][wk + t * 4]     = l0;
            *(unsigned*)&Wl[wr][wk + t * 4 + 2] = l1;
        }
        __syncthreads();
        // prefetch next chunk
        if (kk + 1 < 16) {
            const float* ab = Ap + (size_t)(i0 + ar) * 512 + (kk + 1) * 32 + ak;
            pa[0] = *(const float4*)(ab);      pa[1] = *(const float4*)(ab + 4);
            pa[2] = *(const float4*)(ab + 8);  pa[3] = *(const float4*)(ab + 12);
            const float* wb = W + (size_t)(j0 + wr) * 512 + (kk + 1) * 32 + wk;
            pw[0] = *(const float4*)(wb);      pw[1] = *(const float4*)(wb + 4);
        }
        // compute: 2 k16 steps
#pragma unroll
        for (int k16 = 0; k16 < 2; k16++) {
            const int ko = k16 * 16 + 2 * q;
            unsigned bh[2][2], bl[2][2];
#pragma unroll
            for (int nf = 0; nf < 2; nf++) {
                const int jl = wn * 16 + nf * 8 + grp;
                bh[nf][0] = *(const unsigned*)&Wh[jl][ko];
                bh[nf][1] = *(const unsigned*)&Wh[jl][ko + 8];
                bl[nf][0] = *(const unsigned*)&Wl[jl][ko];
                bl[nf][1] = *(const unsigned*)&Wl[jl][ko + 8];
            }
#pragma unroll
            for (int mf = 0; mf < 4; mf++) {
                const int row = wm * 64 + mf * 16 + grp;
                unsigned a0 = *(const unsigned*)&Ah[row][ko];
                unsigned a1 = *(const unsigned*)&Ah[row + 8][ko];
                unsigned a2 = *(const unsigned*)&Ah[row][ko + 8];
                unsigned a3 = *(const unsigned*)&Ah[row + 8][ko + 8];
                unsigned c0 = *(const unsigned*)&Al[row][ko];
                unsigned c1 = *(const unsigned*)&Al[row + 8][ko];
                unsigned c2 = *(const unsigned*)&Al[row][ko + 8];
                unsigned c3 = *(const unsigned*)&Al[row + 8][ko + 8];
#pragma unroll
                for (int nf = 0; nf < 2; nf++) {
                    mma16816(acc[mf][nf][0], acc[mf][nf][1], acc[mf][nf][2], acc[mf][nf][3],
                             a0, a1, a2, a3, bh[nf][0], bh[nf][1]);
                    mma16816(acc[mf][nf][0], acc[mf][nf][1], acc[mf][nf][2], acc[mf][nf][3],
                             a0, a1, a2, a3, bl[nf][0], bl[nf][1]);
                    mma16816(acc[mf][nf][0], acc[mf][nf][1], acc[mf][nf][2], acc[mf][nf][3],
                             c0, c1, c2, c3, bh[nf][0], bh[nf][1]);
                }
            }
        }
    }

    // epilogue
#pragma unroll
    for (int mf = 0; mf < 4; mf++) {
#pragma unroll
        for (int nf = 0; nf < 2; nf++) {
#pragma unroll
            for (int half = 0; half < 2; half++) {
                const int i = i0 + wm * 64 + mf * 16 + grp + half * 8;
                const int j = j0 + wn * 16 + nf * 8 + 2 * q;
                float v0 = acc[mf][nf][half * 2]     + bias[j];
                float v1 = acc[mf][nf][half * 2 + 1] + bias[j + 1];
                if (DST == 3) {
                    *(float2*)&Cout[(size_t)i * 512 + j] = make_float2(v0, v1);
                    continue;
                }
                if (DST == 0) { v0 *= 0.125f; v1 *= 0.125f; }
                const int b = i >> 9, t = i & 511;
                const int hh = j >> 6, dh = j & 63;
                unsigned hi, lo;
                split2(v0, v1, hi, lo);
                if (DST == 0) {
                    size_t o = ((size_t)(b * NH_ + hh) * T_ + t) * 64 + dh;
                    *(unsigned*)&g_Qh[o] = hi; *(unsigned*)&g_Ql[o] = lo;
                } else if (DST == 1) {
                    size_t o = ((size_t)(b * NH_ + hh) * T_ + t) * 64 + dh;
                    *(unsigned*)&g_Kh[o] = hi; *(unsigned*)&g_Kl[o] = lo;
                } else {
                    __nv_bfloat16 h0 = __float2bfloat16(v0);
                    __nv_bfloat16 h1 = __float2bfloat16(v1);
                    size_t o = ((size_t)(b * NH_ + hh) * 64 + dh) * T_ + t;
                    g_VTh[o]       = h0;
                    g_VTh[o + T_]  = h1;
                    g_VTl[o]       = __float2bfloat16(v0 - __bfloat162float(h0));
                    g_VTl[o + T_]  = __float2bfloat16(v1 - __bfloat162float(h1));
                }
            }
        }
    }
}

// ---------------------------------------------------------------------------
// pos[h][t][b][s] = Q[b,h,t,:] . rel[t,s,:]   (Q pre-scaled by 1/8)
// ---------------------------------------------------------------------------
__global__ __launch_bounds__(128) void pos_kernel(const float* __restrict__ rel) {
    const int t = blockIdx.x, h = blockIdx.y;
    const int tid = threadIdx.x;
    const int wid = tid >> 5, lane = tid & 31;
    const int grp = lane >> 2, q = lane & 3;

    unsigned Bh[4][2], Bl[4][2];
#pragma unroll
    for (int kk = 0; kk < 4; kk++) {
        size_t base = ((size_t)(grp*NH_+h)*T_ + t)*64 + kk*16 + 2*q;
        Bh[kk][0] = *(const unsigned*)&g_Qh[base];
        Bh[kk][1] = *(const unsigned*)&g_Qh[base + 8];
        Bl[kk][0] = *(const unsigned*)&g_Ql[base];
        Bl[kk][1] = *(const unsigned*)&g_Ql[base + 8];
    }

    for (int it = 0; it < 8; it++) {
        const int s0 = it * 64 + wid * 16;
        float c0 = 0.f, c1 = 0.f, c2 = 0.f, c3 = 0.f;
#pragma unroll
        for (int kk = 0; kk < 4; kk++) {
            const float* r0 = rel + ((size_t)t*T_ + s0 + grp)*D_ + h*64 + kk*16 + 2*q;
            const float* r1 = r0 + 8 * D_;
            float2 rA0 = *(const float2*)r0;
            float2 rA2 = *(const float2*)(r0 + 8);
            float2 rA1 = *(const float2*)r1;
            float2 rA3 = *(const float2*)(r1 + 8);
            unsigned ah0, al0, ah1, al1, ah2, al2, ah3, al3;
            split2(rA0.x, rA0.y, ah0, al0);
            split2(rA1.x, rA1.y, ah1, al1);
            split2(rA2.x, rA2.y, ah2, al2);
            split2(rA3.x, rA3.y, ah3, al3);
            mma16816(c0,c1,c2,c3, ah0,ah1,ah2,ah3, Bh[kk][0], Bh[kk][1]);
            mma16816(c0,c1,c2,c3, ah0,ah1,ah2,ah3, Bl[kk][0], Bl[kk][1]);
            mma16816(c0,c1,c2,c3, al0,al1,al2,al3, Bh[kk][0], Bh[kk][1]);
        }
        size_t o = ((size_t)h*T_ + t) * B_;
        g_pos[(o + 2*q    )*T_ + s0 + grp    ] = c0;
        g_pos[(o + 2*q + 1)*T_ + s0 + grp    ] = c1;
        g_pos[(o + 2*q    )*T_ + s0 + grp + 8] = c2;
        g_pos[(o + 2*q + 1)*T_ + s0 + grp + 8] = c3;
    }
}

// ---------------------------------------------------------------------------
// FA2 attention with bias. CTA = (h, 16-t tile), warp = batch b. s-tiles of 16.
// ---------------------------------------------------------------------------
#define KS_B   0
#define KBUF_B 36864
#define KPL_B  18432
#define VS_B   73728
#define VBUF_B 49152
#define VPL_B  24576
#define PS_B   172032
#define PBUF_B 8192
#define SMEM_BYTES 188416

__global__ __launch_bounds__(256, 1) void attn_mma() {
    const int h  = blockIdx.y;
    const int t0 = blockIdx.x * 16;
    extern __shared__ char sm[];
    const unsigned sb = (unsigned)__cvta_generic_to_shared(sm);

    const int tid = threadIdx.x;
    const int wid = tid >> 5;
    const int lane = tid & 31;
    const int grp = lane >> 2, q = lane & 3;

    unsigned QAh[4][4], QAl[4][4];
#pragma unroll
    for (int kk = 0; kk < 4; kk++) {
        size_t base = ((size_t)(wid*NH_+h)*T_ + t0 + grp)*64 + kk*16 + 2*q;
        QAh[kk][0] = *(const unsigned*)&g_Qh[base];
        QAh[kk][1] = *(const unsigned*)&g_Qh[base + 8*64];
        QAh[kk][2] = *(const unsigned*)&g_Qh[base + 8];
        QAh[kk][3] = *(const unsigned*)&g_Qh[base + 8*64 + 8];
        QAl[kk][0] = *(const unsigned*)&g_Ql[base];
        QAl[kk][1] = *(const unsigned*)&g_Ql[base + 8*64];
        QAl[kk][2] = *(const unsigned*)&g_Ql[base + 8];
        QAl[kk][3] = *(const unsigned*)&g_Ql[base + 8*64 + 8];
    }

    auto issue_tile = [&](int s0, int buf) {
        for (int i = tid; i < 2048; i += 256) {            // K
            int q4 = i & 7, row = i >> 3;
            int s = row & 15, b = (row >> 4) & 7, pl = row >> 7;
            const __nv_bfloat16* src =
                (pl ? g_Kl : g_Kh) + ((size_t)(b*NH_+h)*T_ + s0 + s)*64 + q4*8;
            cp16(sb + KS_B + buf*KBUF_B + pl*KPL_B + (b*16 + s)*144 + q4*16, src);
        }
        for (int i = tid; i < 2048; i += 256) {            // V^T
            int q4 = i & 1, row = i >> 1;
            int d = row & 63, b = (row >> 6) & 7, pl = row >> 9;
            const __nv_bfloat16* src =
                (pl ? g_VTl : g_VTh) + ((size_t)(b*NH_+h)*64 + d)*T_ + s0 + q4*8;
            cp16(sb + VS_B + buf*VBUF_B + pl*VPL_B + (b*64 + d)*48 + q4*16, src);
        }
        for (int i = tid; i < 512; i += 256) {             // pos bias
            int q4 = i & 3, row = i >> 2;
            int t = row & 15, b = row >> 4;
            const float* src = g_pos + ((size_t)(h*T_ + t0 + t)*B_ + b)*T_ + s0 + q4*4;
            cp16(sb + PS_B + buf*PBUF_B + (b*16 + t)*64 + q4*16, src);
        }
    };

    issue_tile(0, 0);  cp_commit();
    issue_tile(16, 1); cp_commit();

    float ctx[8][4];
#pragma unroll
    for (int nt = 0; nt < 8; nt++)
#pragma unroll
        for (int i = 0; i < 4; i++) ctx[nt][i] = 0.f;
    float m_a = -1e30f, m_b = -1e30f, l_a = 0.f, l_b = 0.f;

    for (int it = 0; it < 32; it++) {
        const int buf = it & 1;
        if (it == 31) cp_wait<0>(); else cp_wait<1>();
        __syncthreads();

        float sg[2][4];
        const float* pp = (const float*)(sm + PS_B + buf*PBUF_B) + (wid*16 + grp)*16;
#pragma unroll
        for (int ng = 0; ng < 2; ng++) {
            float2 pa = *(const float2*)(pp + ng*8 + 2*q);
            float2 pb = *(const float2*)(pp + 8*16 + ng*8 + 2*q);
            float c0 = pa.x, c1 = pa.y, c2 = pb.x, c3 = pb.y;
#pragma unroll
            for (int kk = 0; kk < 4; kk++) {
                const char* kp = sm + KS_B + buf*KBUF_B + (wid*16 + ng*8 + grp)*144 + kk*32 + q*4;
                unsigned bh0 = *(const unsigned*)kp;
                unsigned bh1 = *(const unsigned*)(kp + 16);
                unsigned bl0 = *(const unsigned*)(kp + KPL_B);
                unsigned bl1 = *(const unsigned*)(kp + KPL_B + 16);
                mma16816(c0,c1,c2,c3, QAh[kk][0],QAh[kk][1],QAh[kk][2],QAh[kk][3], bh0, bh1);
                mma16816(c0,c1,c2,c3, QAh[kk][0],QAh[kk][1],QAh[kk][2],QAh[kk][3], bl0, bl1);
                mma16816(c0,c1,c2,c3, QAl[kk][0],QAl[kk][1],QAl[kk][2],QAl[kk][3], bh0, bh1);
            }
            sg[ng][0] = c0; sg[ng][1] = c1; sg[ng][2] = c2; sg[ng][3] = c3;
        }

        float ma = fmaxf(fmaxf(sg[0][0], sg[0][1]), fmaxf(sg[1][0], sg[1][1]));
        float mb = fmaxf(fmaxf(sg[0][2], sg[0][3]), fmaxf(sg[1][2], sg[1][3]));
        ma = fmaxf(ma, __shfl_xor_sync(0xffffffffu, ma, 1, 4));
        ma = fmaxf(ma, __shfl_xor_sync(0xffffffffu, ma, 2, 4));
        mb = fmaxf(mb, __shfl_xor_sync(0xffffffffu, mb, 1, 4));
        mb = fmaxf(mb, __shfl_xor_sync(0xffffffffu, mb, 2, 4));
        float mna = fmaxf(m_a, ma), mnb = fmaxf(m_b, mb);
        float sca = __expf(m_a - mna), scb = __expf(m_b - mnb);
        float pa0 = __expf(sg[0][0] - mna), pa1 = __expf(sg[0][1] - mna);
        float pa2 = __expf(sg[1][0] - mna), pa3 = __expf(sg[1][1] - mna);
        float pb0 = __expf(sg[0][2] - mnb), pb1 = __expf(sg[0][3] - mnb);
        float pb2 = __expf(sg[1][2] - mnb), pb3 = __expf(sg[1][3] - mnb);
        float la = pa0 + pa1 + pa2 + pa3;
        float lb = pb0 + pb1 + pb2 + pb3;
        la += __shfl_xor_sync(0xffffffffu, la, 1, 4);
        la += __shfl_xor_sync(0xffffffffu, la, 2, 4);
        lb += __shfl_xor_sync(0xffffffffu, lb, 1, 4);
        lb += __shfl_xor_sync(0xffffffffu, lb, 2, 4);
        l_a = l_a * sca + la; l_b = l_b * scb + lb;
        m_a = mna; m_b = mnb;

        unsigned ah0, al0, ah1, al1, ah2, al2, ah3, al3;
        split2(pa0, pa1, ah0, al0);
        split2(pb0, pb1, ah1, al1);
        split2(pa2, pa3, ah2, al2);
        split2(pb2, pb3, ah3, al3);

#pragma unroll
        for (int nt = 0; nt < 8; nt++) {
            ctx[nt][0] *= sca; ctx[nt][1] *= sca;
            ctx[nt][2] *= scb; ctx[nt][3] *= scb;
        }
#pragma unroll
        for (int nt = 0; nt < 8; nt++) {
            const char* vp = sm + VS_B + buf*VBUF_B + (wid*64 + nt*8 + grp)*48 + q*4;
            unsigned bh0 = *(const unsigned*)vp;
            unsigned bh1 = *(const unsigned*)(vp + 16);
            unsigned bl0 = *(const unsigned*)(vp + VPL_B);
            unsigned bl1 = *(const unsigned*)(vp + VPL_B + 16);
            mma16816(ctx[nt][0],ctx[nt][1],ctx[nt][2],ctx[nt][3], ah0,ah1,ah2,ah3, bh0, bh1);
            mma16816(ctx[nt][0],ctx[nt][1],ctx[nt][2],ctx[nt][3], al0,al1,al2,al3, bh0, bh1);
            mma16816(ctx[nt][0],ctx[nt][1],ctx[nt][2],ctx[nt][3], ah0,ah1,ah2,ah3, bl0, bl1);
        }

        __syncthreads();
        if (it + 2 < 32) issue_tile((it + 2) * 16, buf);
        cp_commit();
    }

    const float inva = 1.0f / l_a, invb = 1.0f / l_b;
    float* o0 = g_ctx + ((size_t)wid*T_ + t0 + grp)*D_ + h*64 + 2*q;
    float* o1 = o0 + 8 * D_;
#pragma unroll
    for (int nt = 0; nt < 8; nt++) {
        *(float2*)(o0 + nt*8) = make_float2(ctx[nt][0]*inva, ctx[nt][1]*inva);
        *(float2*)(o1 + nt*8) = make_float2(ctx[nt][2]*invb, ctx[nt][3]*invb);
    }
}

// ---------------------------------------------------------------------------
extern "C" void kernel_launch(void* const* d_in, const int* in_sizes, int n_in,
                              void* d_out, int out_size) {
    const float* x   = (const float*)d_in[0];
    const float* rel = (const float*)d_in[1];
    const float* Wq  = (const float*)d_in[2];
    const float* bq  = (const float*)d_in[3];
    const float* Wk  = (const float*)d_in[4];
    const float* bk  = (const float*)d_in[5];
    const float* Wv  = (const float*)d_in[6];
    const float* bv  = (const float*)d_in[7];
    const float* Wo  = (const float*)d_in[8];
    const float* bo  = (const float*)d_in[9];
    float* out = (float*)d_out;

    cudaFuncSetAttribute(attn_mma, cudaFuncAttributeMaxDynamicSharedMemorySize, SMEM_BYTES);

    dim3 gg(32, 8);   // 4096/128 x 512/64
    mma_gemm<0><<<gg, 256>>>(x, Wq, bq, nullptr);
    mma_gemm<1><<<gg, 256>>>(x, Wk, bk, nullptr);
    mma_gemm<2><<<gg, 256>>>(x, Wv, bv, nullptr);

    pos_kernel<<<dim3(T_, NH_), 128>>>(rel);

    attn_mma<<<dim3(T_ / 16, NH_), 256, SMEM_BYTES>>>();

    mma_gemm<3><<<gg, 256>>>(nullptr, Wo, bo, out);
}

// round 8
// speedup vs baseline: 7.4481x; 1.0299x over previous
#include <cuda_runtime.h>
#include <cuda_bf16.h>
#include <cstdint>
#include <math.h>

#define B_   8
#define T_   512
#define D_   512
#define NH_  8
#define DH_  64

#define PLANE_ELEMS (B_ * NH_ * T_ * DH_)
__device__ __nv_bfloat16 g_Qh[PLANE_ELEMS], g_Ql[PLANE_ELEMS];   // [b][h][t][d], pre-scaled 1/8
__device__ __nv_bfloat16 g_Kh[PLANE_ELEMS], g_Kl[PLANE_ELEMS];   // [b][h][t][d]
__device__ __nv_bfloat16 g_VTh[PLANE_ELEMS], g_VTl[PLANE_ELEMS]; // [b][h][d][t]
__device__ float g_pos[NH_ * T_ * B_ * T_];                      // [h][t][b][s]
__device__ float g_ctx[B_ * T_ * D_];                            // [b][t][h*64+d]

// ---------------- helpers ----------------
__device__ __forceinline__ void cp16(unsigned smem_addr, const void* g) {
    asm volatile("cp.async.cg.shared.global [%0], [%1], 16;\n" :: "r"(smem_addr), "l"(g));
}
__device__ __forceinline__ void cp_commit() { asm volatile("cp.async.commit_group;\n"); }
template <int N> __device__ __forceinline__ void cp_wait() {
    asm volatile("cp.async.wait_group %0;\n" :: "n"(N));
}
__device__ __forceinline__ unsigned pack2(__nv_bfloat16 x, __nv_bfloat16 y) {
    __nv_bfloat162 t; t.x = x; t.y = y;
    return *reinterpret_cast<unsigned*>(&t);
}
__device__ __forceinline__ void split2(float x, float y, unsigned& hi, unsigned& lo) {
    __nv_bfloat16 xh = __float2bfloat16(x), yh = __float2bfloat16(y);
    hi = pack2(xh, yh);
    lo = pack2(__float2bfloat16(x - __bfloat162float(xh)),
               __float2bfloat16(y - __bfloat162float(yh)));
}
__device__ __forceinline__ void mma16816(float& c0, float& c1, float& c2, float& c3,
                                         unsigned a0, unsigned a1, unsigned a2, unsigned a3,
                                         unsigned b0, unsigned b1) {
    asm volatile("mma.sync.aligned.m16n8k16.row.col.f32.bf16.bf16.f32 "
                 "{%0,%1,%2,%3},{%4,%5,%6,%7},{%8,%9},{%0,%1,%2,%3};\n"
                 : "+f"(c0), "+f"(c1), "+f"(c2), "+f"(c3)
                 : "r"(a0), "r"(a1), "r"(a2), "r"(a3), "r"(b0), "r"(b1));
}

// ---------------------------------------------------------------------------
// Tensor-core GEMM: C[i,j] = sum_k A[i,k]*W[j,k] + bias[j]
// ---------------------------------------------------------------------------
template <int DST>
__global__ __launch_bounds__(256) void mma_gemm(const float* __restrict__ A,
                                                const float* __restrict__ W,
                                                const float* __restrict__ bias,
                                                float* __restrict__ Cout) {
    __shared__ __nv_bfloat16 Ah[128][40], Al[128][40];
    __shared__ __nv_bfloat16 Wh[64][40],  Wl[64][40];

    const float* Ap = (DST == 3) ? (const float*)g_ctx : A;
    const int i0 = blockIdx.x * 128, j0 = blockIdx.y * 64;
    const int tid = threadIdx.x;
    const int wid = tid >> 5, lane = tid & 31;
    const int wm = wid & 1, wn = wid >> 1;
    const int grp = lane >> 2, q = lane & 3;

    const int ar = tid >> 1, ak = (tid & 1) * 16;
    const int wr = tid >> 2, wk = (tid & 3) * 8;

    float4 pa[4], pw[2];
    {
        const float* ab = Ap + (size_t)(i0 + ar) * 512 + ak;
        pa[0] = *(const float4*)(ab);      pa[1] = *(const float4*)(ab + 4);
        pa[2] = *(const float4*)(ab + 8);  pa[3] = *(const float4*)(ab + 12);
        const float* wb = W + (size_t)(j0 + wr) * 512 + wk;
        pw[0] = *(const float4*)(wb);      pw[1] = *(const float4*)(wb + 4);
    }

    float acc[4][2][4];
#pragma unroll
    for (int a = 0; a < 4; a++)
#pragma unroll
        for (int b = 0; b < 2; b++)
#pragma unroll
            for (int c = 0; c < 4; c++) acc[a][b][c] = 0.f;

    for (int kk = 0; kk < 16; kk++) {
        __syncthreads();
#pragma unroll
        for (int t = 0; t < 4; t++) {
            unsigned h0, l0, h1, l1;
            split2(pa[t].x, pa[t].y, h0, l0);
            split2(pa[t].z, pa[t].w, h1, l1);
            *(unsigned*)&Ah[ar][ak + t * 4]     = h0;
            *(unsigned*)&Ah[ar][ak + t * 4 + 2] = h1;
            *(unsigned*)&Al[ar][ak + t * 4]     = l0;
            *(unsigned*)&Al[ar][ak + t * 4 + 2] = l1;
        }
#pragma unroll
        for (int t = 0; t < 2; t++) {
            unsigned h0, l0, h1, l1;
            split2(pw[t].x, pw[t].y, h0, l0);
            split2(pw[t].z, pw[t].w, h1, l1);
            *(unsigned*)&Wh[wr][wk + t * 4]     = h0;
            *(unsigned*)&Wh[wr][wk + t * 4 + 2] = h1;
            *(unsigned*)&Wl[wr][wk + t * 4]     = l0;
            *(unsigned*)&Wl[wr][wk + t * 4 + 2] = l1;
        }
        __syncthreads();
        if (kk + 1 < 16) {
            const float* ab = Ap + (size_t)(i0 + ar) * 512 + (kk + 1) * 32 + ak;
            pa[0] = *(const float4*)(ab);      pa[1] = *(const float4*)(ab + 4);
            pa[2] = *(const float4*)(ab + 8);  pa[3] = *(const float4*)(ab + 12);
            const float* wb = W + (size_t)(j0 + wr) * 512 + (kk + 1) * 32 + wk;
            pw[0] = *(const float4*)(wb);      pw[1] = *(const float4*)(wb + 4);
        }
#pragma unroll
        for (int k16 = 0; k16 < 2; k16++) {
            const int ko = k16 * 16 + 2 * q;
            unsigned bh[2][2], bl[2][2];
#pragma unroll
            for (int nf = 0; nf < 2; nf++) {
                const int jl = wn * 16 + nf * 8 + grp;
                bh[nf][0] = *(const unsigned*)&Wh[jl][ko];
                bh[nf][1] = *(const unsigned*)&Wh[jl][ko + 8];
                bl[nf][0] = *(const unsigned*)&Wl[jl][ko];
                bl[nf][1] = *(const unsigned*)&Wl[jl][ko + 8];
            }
#pragma unroll
            for (int mf = 0; mf < 4; mf++) {
                const int row = wm * 64 + mf * 16 + grp;
                unsigned a0 = *(const unsigned*)&Ah[row][ko];
                unsigned a1 = *(const unsigned*)&Ah[row + 8][ko];
                unsigned a2 = *(const unsigned*)&Ah[row][ko + 8];
                unsigned a3 = *(const unsigned*)&Ah[row + 8][ko + 8];
                unsigned c0 = *(const unsigned*)&Al[row][ko];
                unsigned c1 = *(const unsigned*)&Al[row + 8][ko];
                unsigned c2 = *(const unsigned*)&Al[row][ko + 8];
                unsigned c3 = *(const unsigned*)&Al[row + 8][ko + 8];
#pragma unroll
                for (int nf = 0; nf < 2; nf++) {
                    mma16816(acc[mf][nf][0], acc[mf][nf][1], acc[mf][nf][2], acc[mf][nf][3],
                             a0, a1, a2, a3, bh[nf][0], bh[nf][1]);
                    mma16816(acc[mf][nf][0], acc[mf][nf][1], acc[mf][nf][2], acc[mf][nf][3],
                             a0, a1, a2, a3, bl[nf][0], bl[nf][1]);
                    mma16816(acc[mf][nf][0], acc[mf][nf][1], acc[mf][nf][2], acc[mf][nf][3],
                             c0, c1, c2, c3, bh[nf][0], bh[nf][1]);
                }
            }
        }
    }

#pragma unroll
    for (int mf = 0; mf < 4; mf++) {
#pragma unroll
        for (int nf = 0; nf < 2; nf++) {
#pragma unroll
            for (int half = 0; half < 2; half++) {
                const int i = i0 + wm * 64 + mf * 16 + grp + half * 8;
                const int j = j0 + wn * 16 + nf * 8 + 2 * q;
                float v0 = acc[mf][nf][half * 2]     + bias[j];
                float v1 = acc[mf][nf][half * 2 + 1] + bias[j + 1];
                if (DST == 3) {
                    *(float2*)&Cout[(size_t)i * 512 + j] = make_float2(v0, v1);
                    continue;
                }
                if (DST == 0) { v0 *= 0.125f; v1 *= 0.125f; }
                const int b = i >> 9, t = i & 511;
                const int hh = j >> 6, dh = j & 63;
                unsigned hi, lo;
                split2(v0, v1, hi, lo);
                if (DST == 0) {
                    size_t o = ((size_t)(b * NH_ + hh) * T_ + t) * 64 + dh;
                    *(unsigned*)&g_Qh[o] = hi; *(unsigned*)&g_Ql[o] = lo;
                } else if (DST == 1) {
                    size_t o = ((size_t)(b * NH_ + hh) * T_ + t) * 64 + dh;
                    *(unsigned*)&g_Kh[o] = hi; *(unsigned*)&g_Kl[o] = lo;
                } else {
                    __nv_bfloat16 h0 = __float2bfloat16(v0);
                    __nv_bfloat16 h1 = __float2bfloat16(v1);
                    size_t o = ((size_t)(b * NH_ + hh) * 64 + dh) * T_ + t;
                    g_VTh[o]       = h0;
                    g_VTh[o + T_]  = h1;
                    g_VTl[o]       = __float2bfloat16(v0 - __bfloat162float(h0));
                    g_VTl[o + T_]  = __float2bfloat16(v1 - __bfloat162float(h1));
                }
            }
        }
    }
}

// ---------------------------------------------------------------------------
// pos[h][t][b][s] = Q[b,h,t,:] . rel[t,s,:]   (Q pre-scaled by 1/8)
// v2: rel staged through smem via cp.async, double-buffered 64-s blocks.
// CTA = (t, h), 4 warps; warp does the s-strip [blk*64 + wid*16, +16).
// ---------------------------------------------------------------------------
#define PR_STR 68
#define PTILE  (64 * PR_STR)          // floats per buffer (17408 B)

__global__ __launch_bounds__(128) void pos_kernel(const float* __restrict__ rel) {
    __shared__ float Rs[2 * PTILE];   // 34816 B
    const int t = blockIdx.x, h = blockIdx.y;
    const int tid = threadIdx.x;
    const int wid = tid >> 5, lane = tid & 31;
    const int grp = lane >> 2, q = lane & 3;
    const unsigned sb = (unsigned)__cvta_generic_to_shared(Rs);

    // B fragments (Q_t): b = grp, d = kk*16 + 2q (+8)
    unsigned Bh[4][2], Bl[4][2];
#pragma unroll
    for (int kk = 0; kk < 4; kk++) {
        size_t base = ((size_t)(grp*NH_+h)*T_ + t)*64 + kk*16 + 2*q;
        Bh[kk][0] = *(const unsigned*)&g_Qh[base];
        Bh[kk][1] = *(const unsigned*)&g_Qh[base + 8];
        Bl[kk][0] = *(const unsigned*)&g_Ql[base];
        Bl[kk][1] = *(const unsigned*)&g_Ql[base + 8];
    }

    // stage a 64-row s-block of rel[t, s, h*64 .. +64) into buffer buf
    auto issue = [&](int blk, int buf) {
        const float* base = rel + ((size_t)t*T_ + blk*64)*D_ + h*64;
#pragma unroll
        for (int p = 0; p < 8; p++) {
            int c = tid + p * 128;
            int row = c >> 4, col4 = c & 15;
            cp16(sb + (unsigned)(buf*PTILE + row*PR_STR + col4*4)*4,
                 base + (size_t)row*D_ + col4*4);
        }
    };

    issue(0, 0); cp_commit();
    issue(1, 1); cp_commit();

    for (int blk = 0; blk < 8; blk++) {
        const int buf = blk & 1;
        if (blk == 7) cp_wait<0>(); else cp_wait<1>();
        __syncthreads();

        const float* rs = Rs + buf*PTILE + (wid*16 + grp)*PR_STR;
        float c0 = 0.f, c1 = 0.f, c2 = 0.f, c3 = 0.f;
#pragma unroll
        for (int kk = 0; kk < 4; kk++) {
            float2 rA0 = *(const float2*)(rs + kk*16 + 2*q);
            float2 rA2 = *(const float2*)(rs + kk*16 + 2*q + 8);
            float2 rA1 = *(const float2*)(rs + 8*PR_STR + kk*16 + 2*q);
            float2 rA3 = *(const float2*)(rs + 8*PR_STR + kk*16 + 2*q + 8);
            unsigned ah0, al0, ah1, al1, ah2, al2, ah3, al3;
            split2(rA0.x, rA0.y, ah0, al0);
            split2(rA1.x, rA1.y, ah1, al1);
            split2(rA2.x, rA2.y, ah2, al2);
            split2(rA3.x, rA3.y, ah3, al3);
            mma16816(c0,c1,c2,c3, ah0,ah1,ah2,ah3, Bh[kk][0], Bh[kk][1]);
            mma16816(c0,c1,c2,c3, ah0,ah1,ah2,ah3, Bl[kk][0], Bl[kk][1]);
            mma16816(c0,c1,c2,c3, al0,al1,al2,al3, Bh[kk][0], Bh[kk][1]);
        }
        const int s0 = blk * 64 + wid * 16;
        size_t o = ((size_t)h*T_ + t) * B_;
        g_pos[(o + 2*q    )*T_ + s0 + grp    ] = c0;
        g_pos[(o + 2*q + 1)*T_ + s0 + grp    ] = c1;
        g_pos[(o + 2*q    )*T_ + s0 + grp + 8] = c2;
        g_pos[(o + 2*q + 1)*T_ + s0 + grp + 8] = c3;

        __syncthreads();
        if (blk + 2 < 8) issue(blk + 2, buf);
        cp_commit();
    }
}

// ---------------------------------------------------------------------------
// FA2 attention with bias. CTA = (h, 16-t tile), warp = batch b. s-tiles of 16.
// ---------------------------------------------------------------------------
#define KS_B   0
#define KBUF_B 36864
#define KPL_B  18432
#define VS_B   73728
#define VBUF_B 49152
#define VPL_B  24576
#define PS_B   172032
#define PBUF_B 8192
#define SMEM_BYTES 188416

__global__ __launch_bounds__(256, 1) void attn_mma() {
    const int h  = blockIdx.y;
    const int t0 = blockIdx.x * 16;
    extern __shared__ char sm[];
    const unsigned sb = (unsigned)__cvta_generic_to_shared(sm);

    const int tid = threadIdx.x;
    const int wid = tid >> 5;
    const int lane = tid & 31;
    const int grp = lane >> 2, q = lane & 3;

    unsigned QAh[4][4], QAl[4][4];
#pragma unroll
    for (int kk = 0; kk < 4; kk++) {
        size_t base = ((size_t)(wid*NH_+h)*T_ + t0 + grp)*64 + kk*16 + 2*q;
        QAh[kk][0] = *(const unsigned*)&g_Qh[base];
        QAh[kk][1] = *(const unsigned*)&g_Qh[base + 8*64];
        QAh[kk][2] = *(const unsigned*)&g_Qh[base + 8];
        QAh[kk][3] = *(const unsigned*)&g_Qh[base + 8*64 + 8];
        QAl[kk][0] = *(const unsigned*)&g_Ql[base];
        QAl[kk][1] = *(const unsigned*)&g_Ql[base + 8*64];
        QAl[kk][2] = *(const unsigned*)&g_Ql[base + 8];
        QAl[kk][3] = *(const unsigned*)&g_Ql[base + 8*64 + 8];
    }

    auto issue_tile = [&](int s0, int buf) {
        for (int i = tid; i < 2048; i += 256) {            // K
            int q4 = i & 7, row = i >> 3;
            int s = row & 15, b = (row >> 4) & 7, pl = row >> 7;
            const __nv_bfloat16* src =
                (pl ? g_Kl : g_Kh) + ((size_t)(b*NH_+h)*T_ + s0 + s)*64 + q4*8;
            cp16(sb + KS_B + buf*KBUF_B + pl*KPL_B + (b*16 + s)*144 + q4*16, src);
        }
        for (int i = tid; i < 2048; i += 256) {            // V^T
            int q4 = i & 1, row = i >> 1;
            int d = row & 63, b = (row >> 6) & 7, pl = row >> 9;
            const __nv_bfloat16* src =
                (pl ? g_VTl : g_VTh) + ((size_t)(b*NH_+h)*64 + d)*T_ + s0 + q4*8;
            cp16(sb + VS_B + buf*VBUF_B + pl*VPL_B + (b*64 + d)*48 + q4*16, src);
        }
        for (int i = tid; i < 512; i += 256) {             // pos bias
            int q4 = i & 3, row = i >> 2;
            int t = row & 15, b = row >> 4;
            const float* src = g_pos + ((size_t)(h*T_ + t0 + t)*B_ + b)*T_ + s0 + q4*4;
            cp16(sb + PS_B + buf*PBUF_B + (b*16 + t)*64 + q4*16, src);
        }
    };

    issue_tile(0, 0);  cp_commit();
    issue_tile(16, 1); cp_commit();

    float ctx[8][4];
#pragma unroll
    for (int nt = 0; nt < 8; nt++)
#pragma unroll
        for (int i = 0; i < 4; i++) ctx[nt][i] = 0.f;
    float m_a = -1e30f, m_b = -1e30f, l_a = 0.f, l_b = 0.f;

    for (int it = 0; it < 32; it++) {
        const int buf = it & 1;
        if (it == 31) cp_wait<0>(); else cp_wait<1>();
        __syncthreads();

        float sg[2][4];
        const float* pp = (const float*)(sm + PS_B + buf*PBUF_B) + (wid*16 + grp)*16;
#pragma unroll
        for (int ng = 0; ng < 2; ng++) {
            float2 pa = *(const float2*)(pp + ng*8 + 2*q);
            float2 pb = *(const float2*)(pp + 8*16 + ng*8 + 2*q);
            float c0 = pa.x, c1 = pa.y, c2 = pb.x, c3 = pb.y;
#pragma unroll
            for (int kk = 0; kk < 4; kk++) {
                const char* kp = sm + KS_B + buf*KBUF_B + (wid*16 + ng*8 + grp)*144 + kk*32 + q*4;
                unsigned bh0 = *(const unsigned*)kp;
                unsigned bh1 = *(const unsigned*)(kp + 16);
                unsigned bl0 = *(const unsigned*)(kp + KPL_B);
                unsigned bl1 = *(const unsigned*)(kp + KPL_B + 16);
                mma16816(c0,c1,c2,c3, QAh[kk][0],QAh[kk][1],QAh[kk][2],QAh[kk][3], bh0, bh1);
                mma16816(c0,c1,c2,c3, QAh[kk][0],QAh[kk][1],QAh[kk][2],QAh[kk][3], bl0, bl1);
                mma16816(c0,c1,c2,c3, QAl[kk][0],QAl[kk][1],QAl[kk][2],QAl[kk][3], bh0, bh1);
            }
            sg[ng][0] = c0; sg[ng][1] = c1; sg[ng][2] = c2; sg[ng][3] = c3;
        }

        float ma = fmaxf(fmaxf(sg[0][0], sg[0][1]), fmaxf(sg[1][0], sg[1][1]));
        float mb = fmaxf(fmaxf(sg[0][2], sg[0][3]), fmaxf(sg[1][2], sg[1][3]));
        ma = fmaxf(ma, __shfl_xor_sync(0xffffffffu, ma, 1, 4));
        ma = fmaxf(ma, __shfl_xor_sync(0xffffffffu, ma, 2, 4));
        mb = fmaxf(mb, __shfl_xor_sync(0xffffffffu, mb, 1, 4));
        mb = fmaxf(mb, __shfl_xor_sync(0xffffffffu, mb, 2, 4));
        float mna = fmaxf(m_a, ma), mnb = fmaxf(m_b, mb);
        float sca = __expf(m_a - mna), scb = __expf(m_b - mnb);
        float pa0 = __expf(sg[0][0] - mna), pa1 = __expf(sg[0][1] - mna);
        float pa2 = __expf(sg[1][0] - mna), pa3 = __expf(sg[1][1] - mna);
        float pb0 = __expf(sg[0][2] - mnb), pb1 = __expf(sg[0][3] - mnb);
        float pb2 = __expf(sg[1][2] - mnb), pb3 = __expf(sg[1][3] - mnb);
        float la = pa0 + pa1 + pa2 + pa3;
        float lb = pb0 + pb1 + pb2 + pb3;
        la += __shfl_xor_sync(0xffffffffu, la, 1, 4);
        la += __shfl_xor_sync(0xffffffffu, la, 2, 4);
        lb += __shfl_xor_sync(0xffffffffu, lb, 1, 4);
        lb += __shfl_xor_sync(0xffffffffu, lb, 2, 4);
        l_a = l_a * sca + la; l_b = l_b * scb + lb;
        m_a = mna; m_b = mnb;

        unsigned ah0, al0, ah1, al1, ah2, al2, ah3, al3;
        split2(pa0, pa1, ah0, al0);
        split2(pb0, pb1, ah1, al1);
        split2(pa2, pa3, ah2, al2);
        split2(pb2, pb3, ah3, al3);

#pragma unroll
        for (int nt = 0; nt < 8; nt++) {
            ctx[nt][0] *= sca; ctx[nt][1] *= sca;
            ctx[nt][2] *= scb; ctx[nt][3] *= scb;
        }
#pragma unroll
        for (int nt = 0; nt < 8; nt++) {
            const char* vp = sm + VS_B + buf*VBUF_B + (wid*64 + nt*8 + grp)*48 + q*4;
            unsigned bh0 = *(const unsigned*)vp;
            unsigned bh1 = *(const unsigned*)(vp + 16);
            unsigned bl0 = *(const unsigned*)(vp + VPL_B);
            unsigned bl1 = *(const unsigned*)(vp + VPL_B + 16);
            mma16816(ctx[nt][0],ctx[nt][1],ctx[nt][2],ctx[nt][3], ah0,ah1,ah2,ah3, bh0, bh1);
            mma16816(ctx[nt][0],ctx[nt][1],ctx[nt][2],ctx[nt][3], al0,al1,al2,al3, bh0, bh1);
            mma16816(ctx[nt][0],ctx[nt][1],ctx[nt][2],ctx[nt][3], ah0,ah1,ah2,ah3, bl0, bl1);
        }

        __syncthreads();
        if (it + 2 < 32) issue_tile((it + 2) * 16, buf);
        cp_commit();
    }

    const float inva = 1.0f / l_a, invb = 1.0f / l_b;
    float* o0 = g_ctx + ((size_t)wid*T_ + t0 + grp)*D_ + h*64 + 2*q;
    float* o1 = o0 + 8 * D_;
#pragma unroll
    for (int nt = 0; nt < 8; nt++) {
        *(float2*)(o0 + nt*8) = make_float2(ctx[nt][0]*inva, ctx[nt][1]*inva);
        *(float2*)(o1 + nt*8) = make_float2(ctx[nt][2]*invb, ctx[nt][3]*invb);
    }
}

// ---------------------------------------------------------------------------
extern "C" void kernel_launch(void* const* d_in, const int* in_sizes, int n_in,
                              void* d_out, int out_size) {
    const float* x   = (const float*)d_in[0];
    const float* rel = (const float*)d_in[1];
    const float* Wq  = (const float*)d_in[2];
    const float* bq  = (const float*)d_in[3];
    const float* Wk  = (const float*)d_in[4];
    const float* bk  = (const float*)d_in[5];
    const float* Wv  = (const float*)d_in[6];
    const float* bv  = (const float*)d_in[7];
    const float* Wo  = (const float*)d_in[8];
    const float* bo  = (const float*)d_in[9];
    float* out = (float*)d_out;

    cudaFuncSetAttribute(attn_mma, cudaFuncAttributeMaxDynamicSharedMemorySize, SMEM_BYTES);

    dim3 gg(32, 8);
    mma_gemm<0><<<gg, 256>>>(x, Wq, bq, nullptr);
    mma_gemm<1><<<gg, 256>>>(x, Wk, bk, nullptr);
    mma_gemm<2><<<gg, 256>>>(x, Wv, bv, nullptr);

    pos_kernel<<<dim3(T_, NH_), 128>>>(rel);

    attn_mma<<<dim3(T_ / 16, NH_), 256, SMEM_BYTES>>>();

    mma_gemm<3><<<gg, 256>>>(nullptr, Wo, bo, out);
}

// round 9
// speedup vs baseline: 8.3421x; 1.1200x over previous
#include <cuda_runtime.h>
#include <cuda_bf16.h>
#include <cstdint>
#include <math.h>

#define B_   8
#define T_   512
#define D_   512
#define NH_  8
#define DH_  64

#define PLANE_ELEMS (B_ * NH_ * T_ * DH_)
__device__ __nv_bfloat16 g_Qh[PLANE_ELEMS], g_Ql[PLANE_ELEMS];   // [b][h][t][d], pre-scaled 1/8
__device__ __nv_bfloat16 g_Kh[PLANE_ELEMS], g_Kl[PLANE_ELEMS];   // [b][h][t][d]
__device__ __nv_bfloat16 g_VTh[PLANE_ELEMS], g_VTl[PLANE_ELEMS]; // [b][h][d][t]
__device__ float g_pos[NH_ * T_ * B_ * T_];                      // [h][t][b][s]
__device__ float g_ctx[B_ * T_ * D_];                            // [b][t][h*64+d]

__device__ __forceinline__ void cp16(unsigned smem_addr, const void* g) {
    asm volatile("cp.async.cg.shared.global [%0], [%1], 16;\n" :: "r"(smem_addr), "l"(g));
}
__device__ __forceinline__ void cp_commit() { asm volatile("cp.async.commit_group;\n"); }
template <int N> __device__ __forceinline__ void cp_wait() {
    asm volatile("cp.async.wait_group %0;\n" :: "n"(N));
}
__device__ __forceinline__ unsigned pack2(__nv_bfloat16 x, __nv_bfloat16 y) {
    __nv_bfloat162 t; t.x = x; t.y = y;
    return *reinterpret_cast<unsigned*>(&t);
}
__device__ __forceinline__ void split2(float x, float y, unsigned& hi, unsigned& lo) {
    __nv_bfloat16 xh = __float2bfloat16(x), yh = __float2bfloat16(y);
    hi = pack2(xh, yh);
    lo = pack2(__float2bfloat16(x - __bfloat162float(xh)),
               __float2bfloat16(y - __bfloat162float(yh)));
}
__device__ __forceinline__ void mma16816(float& c0, float& c1, float& c2, float& c3,
                                         unsigned a0, unsigned a1, unsigned a2, unsigned a3,
                                         unsigned b0, unsigned b1) {
    asm volatile("mma.sync.aligned.m16n8k16.row.col.f32.bf16.bf16.f32 "
                 "{%0,%1,%2,%3},{%4,%5,%6,%7},{%8,%9},{%0,%1,%2,%3};\n"
                 : "+f"(c0), "+f"(c1), "+f"(c2), "+f"(c3)
                 : "r"(a0), "r"(a1), "r"(a2), "r"(a3), "r"(b0), "r"(b1));
}

// ---------------------------------------------------------------------------
// Tensor-core GEMM (unchanged)
// ---------------------------------------------------------------------------
template <int DST>
__global__ __launch_bounds__(256) void mma_gemm(const float* __restrict__ A,
                                                const float* __restrict__ W,
                                                const float* __restrict__ bias,
                                                float* __restrict__ Cout) {
    __shared__ __nv_bfloat16 Ah[128][40], Al[128][40];
    __shared__ __nv_bfloat16 Wh[64][40],  Wl[64][40];

    const float* Ap = (DST == 3) ? (const float*)g_ctx : A;
    const int i0 = blockIdx.x * 128, j0 = blockIdx.y * 64;
    const int tid = threadIdx.x;
    const int wid = tid >> 5, lane = tid & 31;
    const int wm = wid & 1, wn = wid >> 1;
    const int grp = lane >> 2, q = lane & 3;
    const int ar = tid >> 1, ak = (tid & 1) * 16;
    const int wr = tid >> 2, wk = (tid & 3) * 8;

    float4 pa[4], pw[2];
    {
        const float* ab = Ap + (size_t)(i0 + ar) * 512 + ak;
        pa[0] = *(const float4*)(ab);      pa[1] = *(const float4*)(ab + 4);
        pa[2] = *(const float4*)(ab + 8);  pa[3] = *(const float4*)(ab + 12);
        const float* wb = W + (size_t)(j0 + wr) * 512 + wk;
        pw[0] = *(const float4*)(wb);      pw[1] = *(const float4*)(wb + 4);
    }

    float acc[4][2][4];
#pragma unroll
    for (int a = 0; a < 4; a++)
#pragma unroll
        for (int b = 0; b < 2; b++)
#pragma unroll
            for (int c = 0; c < 4; c++) acc[a][b][c] = 0.f;

    for (int kk = 0; kk < 16; kk++) {
        __syncthreads();
#pragma unroll
        for (int t = 0; t < 4; t++) {
            unsigned h0, l0, h1, l1;
            split2(pa[t].x, pa[t].y, h0, l0);
            split2(pa[t].z, pa[t].w, h1, l1);
            *(unsigned*)&Ah[ar][ak + t * 4]     = h0;
            *(unsigned*)&Ah[ar][ak + t * 4 + 2] = h1;
            *(unsigned*)&Al[ar][ak + t * 4]     = l0;
            *(unsigned*)&Al[ar][ak + t * 4 + 2] = l1;
        }
#pragma unroll
        for (int t = 0; t < 2; t++) {
            unsigned h0, l0, h1, l1;
            split2(pw[t].x, pw[t].y, h0, l0);
            split2(pw[t].z, pw[t].w, h1, l1);
            *(unsigned*)&Wh[wr][wk + t * 4]     = h0;
            *(unsigned*)&Wh[wr][wk + t * 4 + 2] = h1;
            *(unsigned*)&Wl[wr][wk + t * 4]     = l0;
            *(unsigned*)&Wl[wr][wk + t * 4 + 2] = l1;
        }
        __syncthreads();
        if (kk + 1 < 16) {
            const float* ab = Ap + (size_t)(i0 + ar) * 512 + (kk + 1) * 32 + ak;
            pa[0] = *(const float4*)(ab);      pa[1] = *(const float4*)(ab + 4);
            pa[2] = *(const float4*)(ab + 8);  pa[3] = *(const float4*)(ab + 12);
            const float* wb = W + (size_t)(j0 + wr) * 512 + (kk + 1) * 32 + wk;
            pw[0] = *(const float4*)(wb);      pw[1] = *(const float4*)(wb + 4);
        }
#pragma unroll
        for (int k16 = 0; k16 < 2; k16++) {
            const int ko = k16 * 16 + 2 * q;
            unsigned bh[2][2], bl[2][2];
#pragma unroll
            for (int nf = 0; nf < 2; nf++) {
                const int jl = wn * 16 + nf * 8 + grp;
                bh[nf][0] = *(const unsigned*)&Wh[jl][ko];
                bh[nf][1] = *(const unsigned*)&Wh[jl][ko + 8];
                bl[nf][0] = *(const unsigned*)&Wl[jl][ko];
                bl[nf][1] = *(const unsigned*)&Wl[jl][ko + 8];
            }
#pragma unroll
            for (int mf = 0; mf < 4; mf++) {
                const int row = wm * 64 + mf * 16 + grp;
                unsigned a0 = *(const unsigned*)&Ah[row][ko];
                unsigned a1 = *(const unsigned*)&Ah[row + 8][ko];
                unsigned a2 = *(const unsigned*)&Ah[row][ko + 8];
                unsigned a3 = *(const unsigned*)&Ah[row + 8][ko + 8];
                unsigned c0 = *(const unsigned*)&Al[row][ko];
                unsigned c1 = *(const unsigned*)&Al[row + 8][ko];
                unsigned c2 = *(const unsigned*)&Al[row][ko + 8];
                unsigned c3 = *(const unsigned*)&Al[row + 8][ko + 8];
#pragma unroll
                for (int nf = 0; nf < 2; nf++) {
                    mma16816(acc[mf][nf][0], acc[mf][nf][1], acc[mf][nf][2], acc[mf][nf][3],
                             a0, a1, a2, a3, bh[nf][0], bh[nf][1]);
                    mma16816(acc[mf][nf][0], acc[mf][nf][1], acc[mf][nf][2], acc[mf][nf][3],
                             a0, a1, a2, a3, bl[nf][0], bl[nf][1]);
                    mma16816(acc[mf][nf][0], acc[mf][nf][1], acc[mf][nf][2], acc[mf][nf][3],
                             c0, c1, c2, c3, bh[nf][0], bh[nf][1]);
                }
            }
        }
    }

#pragma unroll
    for (int mf = 0; mf < 4; mf++) {
#pragma unroll
        for (int nf = 0; nf < 2; nf++) {
#pragma unroll
            for (int half = 0; half < 2; half++) {
                const int i = i0 + wm * 64 + mf * 16 + grp + half * 8;
                const int j = j0 + wn * 16 + nf * 8 + 2 * q;
                float v0 = acc[mf][nf][half * 2]     + bias[j];
                float v1 = acc[mf][nf][half * 2 + 1] + bias[j + 1];
                if (DST == 3) {
                    *(float2*)&Cout[(size_t)i * 512 + j] = make_float2(v0, v1);
                    continue;
                }
                if (DST == 0) { v0 *= 0.125f; v1 *= 0.125f; }
                const int b = i >> 9, t = i & 511;
                const int hh = j >> 6, dh = j & 63;
                unsigned hi, lo;
                split2(v0, v1, hi, lo);
                if (DST == 0) {
                    size_t o = ((size_t)(b * NH_ + hh) * T_ + t) * 64 + dh;
                    *(unsigned*)&g_Qh[o] = hi; *(unsigned*)&g_Ql[o] = lo;
                } else if (DST == 1) {
                    size_t o = ((size_t)(b * NH_ + hh) * T_ + t) * 64 + dh;
                    *(unsigned*)&g_Kh[o] = hi; *(unsigned*)&g_Kl[o] = lo;
                } else {
                    __nv_bfloat16 h0 = __float2bfloat16(v0);
                    __nv_bfloat16 h1 = __float2bfloat16(v1);
                    size_t o = ((size_t)(b * NH_ + hh) * 64 + dh) * T_ + t;
                    g_VTh[o]       = h0;
                    g_VTh[o + T_]  = h1;
                    g_VTl[o]       = __float2bfloat16(v0 - __bfloat162float(h0));
                    g_VTl[o + T_]  = __float2bfloat16(v1 - __bfloat162float(h1));
                }
            }
        }
    }
}

// ---------------------------------------------------------------------------
// pos kernel (unchanged from R8)
// ---------------------------------------------------------------------------
#define PR_STR 68
#define PTILE  (64 * PR_STR)

__global__ __launch_bounds__(128) void pos_kernel(const float* __restrict__ rel) {
    __shared__ float Rs[2 * PTILE];
    const int t = blockIdx.x, h = blockIdx.y;
    const int tid = threadIdx.x;
    const int wid = tid >> 5, lane = tid & 31;
    const int grp = lane >> 2, q = lane & 3;
    const unsigned sb = (unsigned)__cvta_generic_to_shared(Rs);

    unsigned Bh[4][2], Bl[4][2];
#pragma unroll
    for (int kk = 0; kk < 4; kk++) {
        size_t base = ((size_t)(grp*NH_+h)*T_ + t)*64 + kk*16 + 2*q;
        Bh[kk][0] = *(const unsigned*)&g_Qh[base];
        Bh[kk][1] = *(const unsigned*)&g_Qh[base + 8];
        Bl[kk][0] = *(const unsigned*)&g_Ql[base];
        Bl[kk][1] = *(const unsigned*)&g_Ql[base + 8];
    }

    auto issue = [&](int blk, int buf) {
        const float* base = rel + ((size_t)t*T_ + blk*64)*D_ + h*64;
#pragma unroll
        for (int p = 0; p < 8; p++) {
            int c = tid + p * 128;
            int row = c >> 4, col4 = c & 15;
            cp16(sb + (unsigned)(buf*PTILE + row*PR_STR + col4*4)*4,
                 base + (size_t)row*D_ + col4*4);
        }
    };

    issue(0, 0); cp_commit();
    issue(1, 1); cp_commit();

    for (int blk = 0; blk < 8; blk++) {
        const int buf = blk & 1;
        if (blk == 7) cp_wait<0>(); else cp_wait<1>();
        __syncthreads();

        const float* rs = Rs + buf*PTILE + (wid*16 + grp)*PR_STR;
        float c0 = 0.f, c1 = 0.f, c2 = 0.f, c3 = 0.f;
#pragma unroll
        for (int kk = 0; kk < 4; kk++) {
            float2 rA0 = *(const float2*)(rs + kk*16 + 2*q);
            float2 rA2 = *(const float2*)(rs + kk*16 + 2*q + 8);
            float2 rA1 = *(const float2*)(rs + 8*PR_STR + kk*16 + 2*q);
            float2 rA3 = *(const float2*)(rs + 8*PR_STR + kk*16 + 2*q + 8);
            unsigned ah0, al0, ah1, al1, ah2, al2, ah3, al3;
            split2(rA0.x, rA0.y, ah0, al0);
            split2(rA1.x, rA1.y, ah1, al1);
            split2(rA2.x, rA2.y, ah2, al2);
            split2(rA3.x, rA3.y, ah3, al3);
            mma16816(c0,c1,c2,c3, ah0,ah1,ah2,ah3, Bh[kk][0], Bh[kk][1]);
            mma16816(c0,c1,c2,c3, ah0,ah1,ah2,ah3, Bl[kk][0], Bl[kk][1]);
            mma16816(c0,c1,c2,c3, al0,al1,al2,al3, Bh[kk][0], Bh[kk][1]);
        }
        const int s0 = blk * 64 + wid * 16;
        size_t o = ((size_t)h*T_ + t) * B_;
        g_pos[(o + 2*q    )*T_ + s0 + grp    ] = c0;
        g_pos[(o + 2*q + 1)*T_ + s0 + grp    ] = c1;
        g_pos[(o + 2*q    )*T_ + s0 + grp + 8] = c2;
        g_pos[(o + 2*q + 1)*T_ + s0 + grp + 8] = c3;

        __syncthreads();
        if (blk + 2 < 8) issue(blk + 2, buf);
        cp_commit();
    }
}

// ---------------------------------------------------------------------------
// FA2 attention, t-tile 32 (2 m16 tiles per warp). CTA = (h, 32-t tile).
// warp = batch. grid = 16 x 8 = 128 CTAs (single wave).
// ---------------------------------------------------------------------------
#define KS_B   0
#define KBUF_B 36864
#define KPL_B  18432
#define VS_B   73728
#define VBUF_B 49152
#define VPL_B  24576
#define PS_B   172032
#define PBUF_B 16384
#define SMEM_BYTES 204800

__global__ __launch_bounds__(256, 1) void attn_mma() {
    const int h  = blockIdx.y;
    const int t0 = blockIdx.x * 32;
    extern __shared__ char sm[];
    const unsigned sb = (unsigned)__cvta_generic_to_shared(sm);

    const int tid = threadIdx.x;
    const int wid = tid >> 5;
    const int lane = tid & 31;
    const int grp = lane >> 2, q = lane & 3;

    unsigned QAh[2][4][4], QAl[2][4][4];
#pragma unroll
    for (int mt = 0; mt < 2; mt++)
#pragma unroll
    for (int kk = 0; kk < 4; kk++) {
        size_t base = ((size_t)(wid*NH_+h)*T_ + t0 + mt*16 + grp)*64 + kk*16 + 2*q;
        QAh[mt][kk][0] = *(const unsigned*)&g_Qh[base];
        QAh[mt][kk][1] = *(const unsigned*)&g_Qh[base + 8*64];
        QAh[mt][kk][2] = *(const unsigned*)&g_Qh[base + 8];
        QAh[mt][kk][3] = *(const unsigned*)&g_Qh[base + 8*64 + 8];
        QAl[mt][kk][0] = *(const unsigned*)&g_Ql[base];
        QAl[mt][kk][1] = *(const unsigned*)&g_Ql[base + 8*64];
        QAl[mt][kk][2] = *(const unsigned*)&g_Ql[base + 8];
        QAl[mt][kk][3] = *(const unsigned*)&g_Ql[base + 8*64 + 8];
    }

    auto issue_tile = [&](int s0, int buf) {
        for (int i = tid; i < 2048; i += 256) {            // K
            int q4 = i & 7, row = i >> 3;
            int s = row & 15, b = (row >> 4) & 7, pl = row >> 7;
            const __nv_bfloat16* src =
                (pl ? g_Kl : g_Kh) + ((size_t)(b*NH_+h)*T_ + s0 + s)*64 + q4*8;
            cp16(sb + KS_B + buf*KBUF_B + pl*KPL_B + (b*16 + s)*144 + q4*16, src);
        }
        for (int i = tid; i < 2048; i += 256) {            // V^T
            int q4 = i & 1, row = i >> 1;
            int d = row & 63, b = (row >> 6) & 7, pl = row >> 9;
            const __nv_bfloat16* src =
                (pl ? g_VTl : g_VTh) + ((size_t)(b*NH_+h)*64 + d)*T_ + s0 + q4*8;
            cp16(sb + VS_B + buf*VBUF_B + pl*VPL_B + (b*64 + d)*48 + q4*16, src);
        }
        for (int i = tid; i < 1024; i += 256) {            // pos bias [b][t32][s16]
            int q4 = i & 3, row = i >> 2;
            int t = row & 31, b = row >> 5;
            const float* src = g_pos + ((size_t)(h*T_ + t0 + t)*B_ + b)*T_ + s0 + q4*4;
            cp16(sb + PS_B + buf*PBUF_B + (b*32 + t)*64 + q4*16, src);
        }
    };

    issue_tile(0, 0);  cp_commit();
    issue_tile(16, 1); cp_commit();

    float ctx[2][8][4];
#pragma unroll
    for (int mt = 0; mt < 2; mt++)
#pragma unroll
        for (int nt = 0; nt < 8; nt++)
#pragma unroll
            for (int i = 0; i < 4; i++) ctx[mt][nt][i] = 0.f;
    float m_a[2] = {-1e30f, -1e30f}, m_b[2] = {-1e30f, -1e30f};
    float l_a[2] = {0.f, 0.f},       l_b[2] = {0.f, 0.f};

    for (int it = 0; it < 32; it++) {
        const int buf = it & 1;
        if (it == 31) cp_wait<0>(); else cp_wait<1>();
        __syncthreads();

#pragma unroll
        for (int mt = 0; mt < 2; mt++) {
            float sg[2][4];
            const float* pp = (const float*)(sm + PS_B + buf*PBUF_B) + (wid*32 + mt*16 + grp)*16;
#pragma unroll
            for (int ng = 0; ng < 2; ng++) {
                float2 pa = *(const float2*)(pp + ng*8 + 2*q);
                float2 pb = *(const float2*)(pp + 8*16 + ng*8 + 2*q);
                float c0 = pa.x, c1 = pa.y, c2 = pb.x, c3 = pb.y;
#pragma unroll
                for (int kk = 0; kk < 4; kk++) {
                    const char* kp = sm + KS_B + buf*KBUF_B + (wid*16 + ng*8 + grp)*144 + kk*32 + q*4;
                    unsigned bh0 = *(const unsigned*)kp;
                    unsigned bh1 = *(const unsigned*)(kp + 16);
                    unsigned bl0 = *(const unsigned*)(kp + KPL_B);
                    unsigned bl1 = *(const unsigned*)(kp + KPL_B + 16);
                    mma16816(c0,c1,c2,c3, QAh[mt][kk][0],QAh[mt][kk][1],QAh[mt][kk][2],QAh[mt][kk][3], bh0, bh1);
                    mma16816(c0,c1,c2,c3, QAh[mt][kk][0],QAh[mt][kk][1],QAh[mt][kk][2],QAh[mt][kk][3], bl0, bl1);
                    mma16816(c0,c1,c2,c3, QAl[mt][kk][0],QAl[mt][kk][1],QAl[mt][kk][2],QAl[mt][kk][3], bh0, bh1);
                }
                sg[ng][0] = c0; sg[ng][1] = c1; sg[ng][2] = c2; sg[ng][3] = c3;
            }

            float ma = fmaxf(fmaxf(sg[0][0], sg[0][1]), fmaxf(sg[1][0], sg[1][1]));
            float mb = fmaxf(fmaxf(sg[0][2], sg[0][3]), fmaxf(sg[1][2], sg[1][3]));
            ma = fmaxf(ma, __shfl_xor_sync(0xffffffffu, ma, 1, 4));
            ma = fmaxf(ma, __shfl_xor_sync(0xffffffffu, ma, 2, 4));
            mb = fmaxf(mb, __shfl_xor_sync(0xffffffffu, mb, 1, 4));
            mb = fmaxf(mb, __shfl_xor_sync(0xffffffffu, mb, 2, 4));
            float mna = fmaxf(m_a[mt], ma), mnb = fmaxf(m_b[mt], mb);
            float sca = __expf(m_a[mt] - mna), scb = __expf(m_b[mt] - mnb);
            float pa0 = __expf(sg[0][0] - mna), pa1 = __expf(sg[0][1] - mna);
            float pa2 = __expf(sg[1][0] - mna), pa3 = __expf(sg[1][1] - mna);
            float pb0 = __expf(sg[0][2] - mnb), pb1 = __expf(sg[0][3] - mnb);
            float pb2 = __expf(sg[1][2] - mnb), pb3 = __expf(sg[1][3] - mnb);
            float la = pa0 + pa1 + pa2 + pa3;
            float lb = pb0 + pb1 + pb2 + pb3;
            la += __shfl_xor_sync(0xffffffffu, la, 1, 4);
            la += __shfl_xor_sync(0xffffffffu, la, 2, 4);
            lb += __shfl_xor_sync(0xffffffffu, lb, 1, 4);
            lb += __shfl_xor_sync(0xffffffffu, lb, 2, 4);
            l_a[mt] = l_a[mt] * sca + la; l_b[mt] = l_b[mt] * scb + lb;
            m_a[mt] = mna; m_b[mt] = mnb;

            unsigned ah0, al0, ah1, al1, ah2, al2, ah3, al3;
            split2(pa0, pa1, ah0, al0);
            split2(pb0, pb1, ah1, al1);
            split2(pa2, pa3, ah2, al2);
            split2(pb2, pb3, ah3, al3);

#pragma unroll
            for (int nt = 0; nt < 8; nt++) {
                ctx[mt][nt][0] *= sca; ctx[mt][nt][1] *= sca;
                ctx[mt][nt][2] *= scb; ctx[mt][nt][3] *= scb;
            }
#pragma unroll
            for (int nt = 0; nt < 8; nt++) {
                const char* vp = sm + VS_B + buf*VBUF_B + (wid*64 + nt*8 + grp)*48 + q*4;
                unsigned bh0 = *(const unsigned*)vp;
                unsigned bh1 = *(const unsigned*)(vp + 16);
                unsigned bl0 = *(const unsigned*)(vp + VPL_B);
                unsigned bl1 = *(const unsigned*)(vp + VPL_B + 16);
                mma16816(ctx[mt][nt][0],ctx[mt][nt][1],ctx[mt][nt][2],ctx[mt][nt][3],
                         ah0,ah1,ah2,ah3, bh0, bh1);
                mma16816(ctx[mt][nt][0],ctx[mt][nt][1],ctx[mt][nt][2],ctx[mt][nt][3],
                         al0,al1,al2,al3, bh0, bh1);
                mma16816(ctx[mt][nt][0],ctx[mt][nt][1],ctx[mt][nt][2],ctx[mt][nt][3],
                         ah0,ah1,ah2,ah3, bl0, bl1);
            }
        }

        __syncthreads();
        if (it + 2 < 32) issue_tile((it + 2) * 16, buf);
        cp_commit();
    }

#pragma unroll
    for (int mt = 0; mt < 2; mt++) {
        const float inva = 1.0f / l_a[mt], invb = 1.0f / l_b[mt];
        float* o0 = g_ctx + ((size_t)wid*T_ + t0 + mt*16 + grp)*D_ + h*64 + 2*q;
        float* o1 = o0 + 8 * D_;
#pragma unroll
        for (int nt = 0; nt < 8; nt++) {
            *(float2*)(o0 + nt*8) = make_float2(ctx[mt][nt][0]*inva, ctx[mt][nt][1]*inva);
            *(float2*)(o1 + nt*8) = make_float2(ctx[mt][nt][2]*invb, ctx[mt][nt][3]*invb);
        }
    }
}

// ---------------------------------------------------------------------------
extern "C" void kernel_launch(void* const* d_in, const int* in_sizes, int n_in,
                              void* d_out, int out_size) {
    const float* x   = (const float*)d_in[0];
    const float* rel = (const float*)d_in[1];
    const float* Wq  = (const float*)d_in[2];
    const float* bq  = (const float*)d_in[3];
    const float* Wk  = (const float*)d_in[4];
    const float* bk  = (const float*)d_in[5];
    const float* Wv  = (const float*)d_in[6];
    const float* bv  = (const float*)d_in[7];
    const float* Wo  = (const float*)d_in[8];
    const float* bo  = (const float*)d_in[9];
    float* out = (float*)d_out;

    cudaFuncSetAttribute(attn_mma, cudaFuncAttributeMaxDynamicSharedMemorySize, SMEM_BYTES);

    dim3 gg(32, 8);
    mma_gemm<0><<<gg, 256>>>(x, Wq, bq, nullptr);
    mma_gemm<1><<<gg, 256>>>(x, Wk, bk, nullptr);
    mma_gemm<2><<<gg, 256>>>(x, Wv, bv, nullptr);

    pos_kernel<<<dim3(T_, NH_), 128>>>(rel);

    attn_mma<<<dim3(T_ / 32, NH_), 256, SMEM_BYTES>>>();

    mma_gemm<3><<<gg, 256>>>(nullptr, Wo, bo, out);
}

// round 10
// speedup vs baseline: 9.1365x; 1.0952x over previous
#include <cuda_runtime.h>
#include <cuda_bf16.h>
#include <cstdint>
#include <math.h>

#define B_   8
#define T_   512
#define D_   512
#define NH_  8
#define DH_  64

#define PLANE_ELEMS (B_ * NH_ * T_ * DH_)
__device__ __nv_bfloat16 g_Qh[PLANE_ELEMS], g_Ql[PLANE_ELEMS];   // [b][h][t][d], pre-scaled 1/8
__device__ __nv_bfloat16 g_Kh[PLANE_ELEMS], g_Kl[PLANE_ELEMS];   // [b][h][t][d]
__device__ __nv_bfloat16 g_VTh[PLANE_ELEMS], g_VTl[PLANE_ELEMS]; // [b][h][d][t]
__device__ float g_pos[NH_ * T_ * B_ * T_];                      // [h][t][b][s]

// pre-split inputs / intermediates (bf16 hi/lo planes)
__device__ __nv_bfloat16 g_Xh[4096 * 512], g_Xl[4096 * 512];     // x rows
__device__ __nv_bfloat16 g_CXh[4096 * 512], g_CXl[4096 * 512];   // ctx rows
__device__ __nv_bfloat16 g_Wqh[512 * 512], g_Wql[512 * 512];
__device__ __nv_bfloat16 g_Wkh[512 * 512], g_Wkl[512 * 512];
__device__ __nv_bfloat16 g_Wvh[512 * 512], g_Wvl[512 * 512];
__device__ __nv_bfloat16 g_Woh[512 * 512], g_Wol[512 * 512];

__device__ __forceinline__ void cp16(unsigned smem_addr, const void* g) {
    asm volatile("cp.async.cg.shared.global [%0], [%1], 16;\n" :: "r"(smem_addr), "l"(g));
}
__device__ __forceinline__ void cp_commit() { asm volatile("cp.async.commit_group;\n"); }
template <int N> __device__ __forceinline__ void cp_wait() {
    asm volatile("cp.async.wait_group %0;\n" :: "n"(N));
}
__device__ __forceinline__ unsigned pack2(__nv_bfloat16 x, __nv_bfloat16 y) {
    __nv_bfloat162 t; t.x = x; t.y = y;
    return *reinterpret_cast<unsigned*>(&t);
}
__device__ __forceinline__ void split2(float x, float y, unsigned& hi, unsigned& lo) {
    __nv_bfloat16 xh = __float2bfloat16(x), yh = __float2bfloat16(y);
    hi = pack2(xh, yh);
    lo = pack2(__float2bfloat16(x - __bfloat162float(xh)),
               __float2bfloat16(y - __bfloat162float(yh)));
}
__device__ __forceinline__ void mma16816(float& c0, float& c1, float& c2, float& c3,
                                         unsigned a0, unsigned a1, unsigned a2, unsigned a3,
                                         unsigned b0, unsigned b1) {
    asm volatile("mma.sync.aligned.m16n8k16.row.col.f32.bf16.bf16.f32 "
                 "{%0,%1,%2,%3},{%4,%5,%6,%7},{%8,%9},{%0,%1,%2,%3};\n"
                 : "+f"(c0), "+f"(c1), "+f"(c2), "+f"(c3)
                 : "r"(a0), "r"(a1), "r"(a2), "r"(a3), "r"(b0), "r"(b1));
}

// ---------------------------------------------------------------------------
// split x + 4 weights into bf16 hi/lo planes (once)
// ---------------------------------------------------------------------------
__global__ __launch_bounds__(256) void split_kernel(const float* __restrict__ x,
                                                    const float* __restrict__ Wq,
                                                    const float* __restrict__ Wk,
                                                    const float* __restrict__ Wv,
                                                    const float* __restrict__ Wo) {
    const int seg = blockIdx.y;
    const float* src;
    __nv_bfloat16 *dh, *dl;
    int n;  // float2 pairs
    if (seg == 0)      { src = x;  dh = g_Xh;  dl = g_Xl;  n = 4096 * 512 / 2; }
    else if (seg == 1) { src = Wq; dh = g_Wqh; dl = g_Wql; n = 512 * 512 / 2; }
    else if (seg == 2) { src = Wk; dh = g_Wkh; dl = g_Wkl; n = 512 * 512 / 2; }
    else if (seg == 3) { src = Wv; dh = g_Wvh; dl = g_Wvl; n = 512 * 512 / 2; }
    else               { src = Wo; dh = g_Woh; dl = g_Wol; n = 512 * 512 / 2; }
    for (int i = blockIdx.x * 256 + threadIdx.x; i < n; i += gridDim.x * 256) {
        float2 v = ((const float2*)src)[i];
        unsigned hi, lo;
        split2(v.x, v.y, hi, lo);
        ((unsigned*)dh)[i] = hi;
        ((unsigned*)dl)[i] = lo;
    }
}

// ---------------------------------------------------------------------------
// bf16-plane GEMM: C[i,j] = sum_k A[i,k]*W[j,k] (+bias). cp.async 2-stage,
// k-chunk 64, CTA 128x64, 256 thr (2x4 warps, warp tile 64x16).
// DST 0: Q planes (scaled 1/8)  1: K planes  2: V^T planes  3: fp32 out+bias
// ---------------------------------------------------------------------------
#define GA_STR 72                       // bf16 row stride
#define GA_PLB (128 * GA_STR * 2)       // A plane bytes  = 18432
#define SA_BUF (2 * GA_PLB)             // A buf (2 planes) = 36864
#define GW_PLB (64 * GA_STR * 2)        // W plane bytes  = 9216
#define SW_BUF (2 * GW_PLB)             // 18432
#define SW_B   (2 * SA_BUF)             // 73728
#define GSM_BYTES (SW_B + 2 * SW_BUF)   // 110592

template <int DST>
__global__ __launch_bounds__(256) void mma_gemm2(const float* __restrict__ bias,
                                                 float* __restrict__ Cout) {
    extern __shared__ char gsm[];
    const unsigned sb = (unsigned)__cvta_generic_to_shared(gsm);

    const __nv_bfloat16 *Aph, *Apl, *Wph, *Wpl;
    if (DST == 3) { Aph = g_CXh; Apl = g_CXl; } else { Aph = g_Xh; Apl = g_Xl; }
    if (DST == 0)      { Wph = g_Wqh; Wpl = g_Wql; }
    else if (DST == 1) { Wph = g_Wkh; Wpl = g_Wkl; }
    else if (DST == 2) { Wph = g_Wvh; Wpl = g_Wvl; }
    else               { Wph = g_Woh; Wpl = g_Wol; }

    const int i0 = blockIdx.x * 128, j0 = blockIdx.y * 64;
    const int tid = threadIdx.x;
    const int wid = tid >> 5, lane = tid & 31;
    const int wm = wid & 1, wn = wid >> 1;
    const int grp = lane >> 2, q = lane & 3;

    auto issue = [&](int st, int buf) {
        const int k0 = st * 64;
        for (int c = tid; c < 2048; c += 256) {          // A: 128r x 64c x 2pl
            int col8 = c & 7, row = (c >> 3) & 127, pl = c >> 10;
            const __nv_bfloat16* src = (pl ? Apl : Aph) + (size_t)(i0 + row) * 512 + k0 + col8 * 8;
            cp16(sb + buf * SA_BUF + pl * GA_PLB + (row * GA_STR + col8 * 8) * 2, src);
        }
        for (int c = tid; c < 1024; c += 256) {          // W: 64r x 64c x 2pl
            int col8 = c & 7, row = (c >> 3) & 63, pl = c >> 9;
            const __nv_bfloat16* src = (pl ? Wpl : Wph) + (size_t)(j0 + row) * 512 + k0 + col8 * 8;
            cp16(sb + SW_B + buf * SW_BUF + pl * GW_PLB + (row * GA_STR + col8 * 8) * 2, src);
        }
    };

    issue(0, 0); cp_commit();
    issue(1, 1); cp_commit();

    float acc[4][2][4];
#pragma unroll
    for (int a = 0; a < 4; a++)
#pragma unroll
        for (int b = 0; b < 2; b++)
#pragma unroll
            for (int c = 0; c < 4; c++) acc[a][b][c] = 0.f;

    for (int st = 0; st < 8; st++) {
        const int buf = st & 1;
        if (st == 7) cp_wait<0>(); else cp_wait<1>();
        __syncthreads();

        const char* Ab = gsm + buf * SA_BUF;
        const char* Wb = gsm + SW_B + buf * SW_BUF;
#pragma unroll
        for (int k16 = 0; k16 < 4; k16++) {
            const int ko = k16 * 16 + 2 * q;
            unsigned bh[2][2], bl[2][2];
#pragma unroll
            for (int nf = 0; nf < 2; nf++) {
                const int jl = wn * 16 + nf * 8 + grp;
                const char* wp = Wb + (jl * GA_STR + ko) * 2;
                bh[nf][0] = *(const unsigned*)wp;
                bh[nf][1] = *(const unsigned*)(wp + 16);
                bl[nf][0] = *(const unsigned*)(wp + GW_PLB);
                bl[nf][1] = *(const unsigned*)(wp + GW_PLB + 16);
            }
#pragma unroll
            for (int mf = 0; mf < 4; mf++) {
                const int row = wm * 64 + mf * 16 + grp;
                const char* ap = Ab + (row * GA_STR + ko) * 2;
                unsigned a0 = *(const unsigned*)ap;
                unsigned a1 = *(const unsigned*)(ap + 8 * GA_STR * 2);
                unsigned a2 = *(const unsigned*)(ap + 16);
                unsigned a3 = *(const unsigned*)(ap + 8 * GA_STR * 2 + 16);
                unsigned c0 = *(const unsigned*)(ap + GA_PLB);
                unsigned c1 = *(const unsigned*)(ap + GA_PLB + 8 * GA_STR * 2);
                unsigned c2 = *(const unsigned*)(ap + GA_PLB + 16);
                unsigned c3 = *(const unsigned*)(ap + GA_PLB + 8 * GA_STR * 2 + 16);
#pragma unroll
                for (int nf = 0; nf < 2; nf++) {
                    mma16816(acc[mf][nf][0], acc[mf][nf][1], acc[mf][nf][2], acc[mf][nf][3],
                             a0, a1, a2, a3, bh[nf][0], bh[nf][1]);
                    mma16816(acc[mf][nf][0], acc[mf][nf][1], acc[mf][nf][2], acc[mf][nf][3],
                             a0, a1, a2, a3, bl[nf][0], bl[nf][1]);
                    mma16816(acc[mf][nf][0], acc[mf][nf][1], acc[mf][nf][2], acc[mf][nf][3],
                             c0, c1, c2, c3, bh[nf][0], bh[nf][1]);
                }
            }
        }
        __syncthreads();
        if (st + 2 < 8) issue(st + 2, buf);
        cp_commit();
    }

#pragma unroll
    for (int mf = 0; mf < 4; mf++) {
#pragma unroll
        for (int nf = 0; nf < 2; nf++) {
#pragma unroll
            for (int half = 0; half < 2; half++) {
                const int i = i0 + wm * 64 + mf * 16 + grp + half * 8;
                const int j = j0 + wn * 16 + nf * 8 + 2 * q;
                float v0 = acc[mf][nf][half * 2]     + bias[j];
                float v1 = acc[mf][nf][half * 2 + 1] + bias[j + 1];
                if (DST == 3) {
                    *(float2*)&Cout[(size_t)i * 512 + j] = make_float2(v0, v1);
                    continue;
                }
                if (DST == 0) { v0 *= 0.125f; v1 *= 0.125f; }
                const int b = i >> 9, t = i & 511;
                const int hh = j >> 6, dh = j & 63;
                unsigned hi, lo;
                split2(v0, v1, hi, lo);
                if (DST == 0) {
                    size_t o = ((size_t)(b * NH_ + hh) * T_ + t) * 64 + dh;
                    *(unsigned*)&g_Qh[o] = hi; *(unsigned*)&g_Ql[o] = lo;
                } else if (DST == 1) {
                    size_t o = ((size_t)(b * NH_ + hh) * T_ + t) * 64 + dh;
                    *(unsigned*)&g_Kh[o] = hi; *(unsigned*)&g_Kl[o] = lo;
                } else {
                    __nv_bfloat16 h0 = __float2bfloat16(v0);
                    __nv_bfloat16 h1 = __float2bfloat16(v1);
                    size_t o = ((size_t)(b * NH_ + hh) * 64 + dh) * T_ + t;
                    g_VTh[o]       = h0;
                    g_VTh[o + T_]  = h1;
                    g_VTl[o]       = __float2bfloat16(v0 - __bfloat162float(h0));
                    g_VTl[o + T_]  = __float2bfloat16(v1 - __bfloat162float(h1));
                }
            }
        }
    }
}

// ---------------------------------------------------------------------------
// pos kernel (unchanged)
// ---------------------------------------------------------------------------
#define PR_STR 68
#define PTILE  (64 * PR_STR)

__global__ __launch_bounds__(128) void pos_kernel(const float* __restrict__ rel) {
    __shared__ float Rs[2 * PTILE];
    const int t = blockIdx.x, h = blockIdx.y;
    const int tid = threadIdx.x;
    const int wid = tid >> 5, lane = tid & 31;
    const int grp = lane >> 2, q = lane & 3;
    const unsigned sb = (unsigned)__cvta_generic_to_shared(Rs);

    unsigned Bh[4][2], Bl[4][2];
#pragma unroll
    for (int kk = 0; kk < 4; kk++) {
        size_t base = ((size_t)(grp*NH_+h)*T_ + t)*64 + kk*16 + 2*q;
        Bh[kk][0] = *(const unsigned*)&g_Qh[base];
        Bh[kk][1] = *(const unsigned*)&g_Qh[base + 8];
        Bl[kk][0] = *(const unsigned*)&g_Ql[base];
        Bl[kk][1] = *(const unsigned*)&g_Ql[base + 8];
    }

    auto issue = [&](int blk, int buf) {
        const float* base = rel + ((size_t)t*T_ + blk*64)*D_ + h*64;
#pragma unroll
        for (int p = 0; p < 8; p++) {
            int c = tid + p * 128;
            int row = c >> 4, col4 = c & 15;
            cp16(sb + (unsigned)(buf*PTILE + row*PR_STR + col4*4)*4,
                 base + (size_t)row*D_ + col4*4);
        }
    };

    issue(0, 0); cp_commit();
    issue(1, 1); cp_commit();

    for (int blk = 0; blk < 8; blk++) {
        const int buf = blk & 1;
        if (blk == 7) cp_wait<0>(); else cp_wait<1>();
        __syncthreads();

        const float* rs = Rs + buf*PTILE + (wid*16 + grp)*PR_STR;
        float c0 = 0.f, c1 = 0.f, c2 = 0.f, c3 = 0.f;
#pragma unroll
        for (int kk = 0; kk < 4; kk++) {
            float2 rA0 = *(const float2*)(rs + kk*16 + 2*q);
            float2 rA2 = *(const float2*)(rs + kk*16 + 2*q + 8);
            float2 rA1 = *(const float2*)(rs + 8*PR_STR + kk*16 + 2*q);
            float2 rA3 = *(const float2*)(rs + 8*PR_STR + kk*16 + 2*q + 8);
            unsigned ah0, al0, ah1, al1, ah2, al2, ah3, al3;
            split2(rA0.x, rA0.y, ah0, al0);
            split2(rA1.x, rA1.y, ah1, al1);
            split2(rA2.x, rA2.y, ah2, al2);
            split2(rA3.x, rA3.y, ah3, al3);
            mma16816(c0,c1,c2,c3, ah0,ah1,ah2,ah3, Bh[kk][0], Bh[kk][1]);
            mma16816(c0,c1,c2,c3, ah0,ah1,ah2,ah3, Bl[kk][0], Bl[kk][1]);
            mma16816(c0,c1,c2,c3, al0,al1,al2,al3, Bh[kk][0], Bh[kk][1]);
        }
        const int s0 = blk * 64 + wid * 16;
        size_t o = ((size_t)h*T_ + t) * B_;
        g_pos[(o + 2*q    )*T_ + s0 + grp    ] = c0;
        g_pos[(o + 2*q + 1)*T_ + s0 + grp    ] = c1;
        g_pos[(o + 2*q    )*T_ + s0 + grp + 8] = c2;
        g_pos[(o + 2*q + 1)*T_ + s0 + grp + 8] = c3;

        __syncthreads();
        if (blk + 2 < 8) issue(blk + 2, buf);
        cp_commit();
    }
}

// ---------------------------------------------------------------------------
// FA2 attention, t-tile 32, warp = batch; epilogue writes ctx bf16 planes.
// ---------------------------------------------------------------------------
#define KS_B   0
#define KBUF_B 36864
#define KPL_B  18432
#define VS_B   73728
#define VBUF_B 49152
#define VPL_B  24576
#define PS_B   172032
#define PBUF_B 16384
#define SMEM_BYTES 204800

__global__ __launch_bounds__(256, 1) void attn_mma() {
    const int h  = blockIdx.y;
    const int t0 = blockIdx.x * 32;
    extern __shared__ char sm[];
    const unsigned sb = (unsigned)__cvta_generic_to_shared(sm);

    const int tid = threadIdx.x;
    const int wid = tid >> 5;
    const int lane = tid & 31;
    const int grp = lane >> 2, q = lane & 3;

    unsigned QAh[2][4][4], QAl[2][4][4];
#pragma unroll
    for (int mt = 0; mt < 2; mt++)
#pragma unroll
    for (int kk = 0; kk < 4; kk++) {
        size_t base = ((size_t)(wid*NH_+h)*T_ + t0 + mt*16 + grp)*64 + kk*16 + 2*q;
        QAh[mt][kk][0] = *(const unsigned*)&g_Qh[base];
        QAh[mt][kk][1] = *(const unsigned*)&g_Qh[base + 8*64];
        QAh[mt][kk][2] = *(const unsigned*)&g_Qh[base + 8];
        QAh[mt][kk][3] = *(const unsigned*)&g_Qh[base + 8*64 + 8];
        QAl[mt][kk][0] = *(const unsigned*)&g_Ql[base];
        QAl[mt][kk][1] = *(const unsigned*)&g_Ql[base + 8*64];
        QAl[mt][kk][2] = *(const unsigned*)&g_Ql[base + 8];
        QAl[mt][kk][3] = *(const unsigned*)&g_Ql[base + 8*64 + 8];
    }

    auto issue_tile = [&](int s0, int buf) {
        for (int i = tid; i < 2048; i += 256) {            // K
            int q4 = i & 7, row = i >> 3;
            int s = row & 15, b = (row >> 4) & 7, pl = row >> 7;
            const __nv_bfloat16* src =
                (pl ? g_Kl : g_Kh) + ((size_t)(b*NH_+h)*T_ + s0 + s)*64 + q4*8;
            cp16(sb + KS_B + buf*KBUF_B + pl*KPL_B + (b*16 + s)*144 + q4*16, src);
        }
        for (int i = tid; i < 2048; i += 256) {            // V^T
            int q4 = i & 1, row = i >> 1;
            int d = row & 63, b = (row >> 6) & 7, pl = row >> 9;
            const __nv_bfloat16* src =
                (pl ? g_VTl : g_VTh) + ((size_t)(b*NH_+h)*64 + d)*T_ + s0 + q4*8;
            cp16(sb + VS_B + buf*VBUF_B + pl*VPL_B + (b*64 + d)*48 + q4*16, src);
        }
        for (int i = tid; i < 1024; i += 256) {            // pos bias
            int q4 = i & 3, row = i >> 2;
            int t = row & 31, b = row >> 5;
            const float* src = g_pos + ((size_t)(h*T_ + t0 + t)*B_ + b)*T_ + s0 + q4*4;
            cp16(sb + PS_B + buf*PBUF_B + (b*32 + t)*64 + q4*16, src);
        }
    };

    issue_tile(0, 0);  cp_commit();
    issue_tile(16, 1); cp_commit();

    float ctx[2][8][4];
#pragma unroll
    for (int mt = 0; mt < 2; mt++)
#pragma unroll
        for (int nt = 0; nt < 8; nt++)
#pragma unroll
            for (int i = 0; i < 4; i++) ctx[mt][nt][i] = 0.f;
    float m_a[2] = {-1e30f, -1e30f}, m_b[2] = {-1e30f, -1e30f};
    float l_a[2] = {0.f, 0.f},       l_b[2] = {0.f, 0.f};

    for (int it = 0; it < 32; it++) {
        const int buf = it & 1;
        if (it == 31) cp_wait<0>(); else cp_wait<1>();
        __syncthreads();

#pragma unroll
        for (int mt = 0; mt < 2; mt++) {
            float sg[2][4];
            const float* pp = (const float*)(sm + PS_B + buf*PBUF_B) + (wid*32 + mt*16 + grp)*16;
#pragma unroll
            for (int ng = 0; ng < 2; ng++) {
                float2 pa = *(const float2*)(pp + ng*8 + 2*q);
                float2 pb = *(const float2*)(pp + 8*16 + ng*8 + 2*q);
                float c0 = pa.x, c1 = pa.y, c2 = pb.x, c3 = pb.y;
#pragma unroll
                for (int kk = 0; kk < 4; kk++) {
                    const char* kp = sm + KS_B + buf*KBUF_B + (wid*16 + ng*8 + grp)*144 + kk*32 + q*4;
                    unsigned bh0 = *(const unsigned*)kp;
                    unsigned bh1 = *(const unsigned*)(kp + 16);
                    unsigned bl0 = *(const unsigned*)(kp + KPL_B);
                    unsigned bl1 = *(const unsigned*)(kp + KPL_B + 16);
                    mma16816(c0,c1,c2,c3, QAh[mt][kk][0],QAh[mt][kk][1],QAh[mt][kk][2],QAh[mt][kk][3], bh0, bh1);
                    mma16816(c0,c1,c2,c3, QAh[mt][kk][0],QAh[mt][kk][1],QAh[mt][kk][2],QAh[mt][kk][3], bl0, bl1);
                    mma16816(c0,c1,c2,c3, QAl[mt][kk][0],QAl[mt][kk][1],QAl[mt][kk][2],QAl[mt][kk][3], bh0, bh1);
                }
                sg[ng][0] = c0; sg[ng][1] = c1; sg[ng][2] = c2; sg[ng][3] = c3;
            }

            float ma = fmaxf(fmaxf(sg[0][0], sg[0][1]), fmaxf(sg[1][0], sg[1][1]));
            float mb = fmaxf(fmaxf(sg[0][2], sg[0][3]), fmaxf(sg[1][2], sg[1][3]));
            ma = fmaxf(ma, __shfl_xor_sync(0xffffffffu, ma, 1, 4));
            ma = fmaxf(ma, __shfl_xor_sync(0xffffffffu, ma, 2, 4));
            mb = fmaxf(mb, __shfl_xor_sync(0xffffffffu, mb, 1, 4));
            mb = fmaxf(mb, __shfl_xor_sync(0xffffffffu, mb, 2, 4));
            float mna = fmaxf(m_a[mt], ma), mnb = fmaxf(m_b[mt], mb);
            float sca = __expf(m_a[mt] - mna), scb = __expf(m_b[mt] - mnb);
            float pa0 = __expf(sg[0][0] - mna), pa1 = __expf(sg[0][1] - mna);
            float pa2 = __expf(sg[1][0] - mna), pa3 = __expf(sg[1][1] - mna);
            float pb0 = __expf(sg[0][2] - mnb), pb1 = __expf(sg[0][3] - mnb);
            float pb2 = __expf(sg[1][2] - mnb), pb3 = __expf(sg[1][3] - mnb);
            float la = pa0 + pa1 + pa2 + pa3;
            float lb = pb0 + pb1 + pb2 + pb3;
            la += __shfl_xor_sync(0xffffffffu, la, 1, 4);
            la += __shfl_xor_sync(0xffffffffu, la, 2, 4);
            lb += __shfl_xor_sync(0xffffffffu, lb, 1, 4);
            lb += __shfl_xor_sync(0xffffffffu, lb, 2, 4);
            l_a[mt] = l_a[mt] * sca + la; l_b[mt] = l_b[mt] * scb + lb;
            m_a[mt] = mna; m_b[mt] = mnb;

            unsigned ah0, al0, ah1, al1, ah2, al2, ah3, al3;
            split2(pa0, pa1, ah0, al0);
            split2(pb0, pb1, ah1, al1);
            split2(pa2, pa3, ah2, al2);
            split2(pb2, pb3, ah3, al3);

#pragma unroll
            for (int nt = 0; nt < 8; nt++) {
                ctx[mt][nt][0] *= sca; ctx[mt][nt][1] *= sca;
                ctx[mt][nt][2] *= scb; ctx[mt][nt][3] *= scb;
            }
#pragma unroll
            for (int nt = 0; nt < 8; nt++) {
                const char* vp = sm + VS_B + buf*VBUF_B + (wid*64 + nt*8 + grp)*48 + q*4;
                unsigned bh0 = *(const unsigned*)vp;
                unsigned bh1 = *(const unsigned*)(vp + 16);
                unsigned bl0 = *(const unsigned*)(vp + VPL_B);
                unsigned bl1 = *(const unsigned*)(vp + VPL_B + 16);
                mma16816(ctx[mt][nt][0],ctx[mt][nt][1],ctx[mt][nt][2],ctx[mt][nt][3],
                         ah0,ah1,ah2,ah3, bh0, bh1);
                mma16816(ctx[mt][nt][0],ctx[mt][nt][1],ctx[mt][nt][2],ctx[mt][nt][3],
                         al0,al1,al2,al3, bh0, bh1);
                mma16816(ctx[mt][nt][0],ctx[mt][nt][1],ctx[mt][nt][2],ctx[mt][nt][3],
                         ah0,ah1,ah2,ah3, bl0, bl1);
            }
        }

        __syncthreads();
        if (it + 2 < 32) issue_tile((it + 2) * 16, buf);
        cp_commit();
    }

#pragma unroll
    for (int mt = 0; mt < 2; mt++) {
        const float inva = 1.0f / l_a[mt], invb = 1.0f / l_b[mt];
        size_t r0 = ((size_t)wid*T_ + t0 + mt*16 + grp)*512 + h*64 + 2*q;
        size_t r1 = r0 + 8 * 512;
#pragma unroll
        for (int nt = 0; nt < 8; nt++) {
            unsigned hi, lo;
            split2(ctx[mt][nt][0]*inva, ctx[mt][nt][1]*inva, hi, lo);
            *(unsigned*)&g_CXh[r0 + nt*8] = hi;
            *(unsigned*)&g_CXl[r0 + nt*8] = lo;
            split2(ctx[mt][nt][2]*invb, ctx[mt][nt][3]*invb, hi, lo);
            *(unsigned*)&g_CXh[r1 + nt*8] = hi;
            *(unsigned*)&g_CXl[r1 + nt*8] = lo;
        }
    }
}

// ---------------------------------------------------------------------------
extern "C" void kernel_launch(void* const* d_in, const int* in_sizes, int n_in,
                              void* d_out, int out_size) {
    const float* x   = (const float*)d_in[0];
    const float* rel = (const float*)d_in[1];
    const float* Wq  = (const float*)d_in[2];
    const float* bq  = (const float*)d_in[3];
    const float* Wk  = (const float*)d_in[4];
    const float* bk  = (const float*)d_in[5];
    const float* Wv  = (const float*)d_in[6];
    const float* bv  = (const float*)d_in[7];
    const float* Wo  = (const float*)d_in[8];
    const float* bo  = (const float*)d_in[9];
    float* out = (float*)d_out;

    cudaFuncSetAttribute(attn_mma, cudaFuncAttributeMaxDynamicSharedMemorySize, SMEM_BYTES);
    cudaFuncSetAttribute(mma_gemm2<0>, cudaFuncAttributeMaxDynamicSharedMemorySize, GSM_BYTES);
    cudaFuncSetAttribute(mma_gemm2<1>, cudaFuncAttributeMaxDynamicSharedMemorySize, GSM_BYTES);
    cudaFuncSetAttribute(mma_gemm2<2>, cudaFuncAttributeMaxDynamicSharedMemorySize, GSM_BYTES);
    cudaFuncSetAttribute(mma_gemm2<3>, cudaFuncAttributeMaxDynamicSharedMemorySize, GSM_BYTES);

    split_kernel<<<dim3(256, 5), 256>>>(x, Wq, Wk, Wv, Wo);

    dim3 gg(32, 8);
    mma_gemm2<0><<<gg, 256, GSM_BYTES>>>(bq, nullptr);
    mma_gemm2<1><<<gg, 256, GSM_BYTES>>>(bk, nullptr);
    mma_gemm2<2><<<gg, 256, GSM_BYTES>>>(bv, nullptr);

    pos_kernel<<<dim3(T_, NH_), 128>>>(rel);

    attn_mma<<<dim3(T_ / 32, NH_), 256, SMEM_BYTES>>>();

    mma_gemm2<3><<<gg, 256, GSM_BYTES>>>(bo, out);
}